// round 7
// baseline (speedup 1.0000x reference)
#include <cuda_runtime.h>
#include <cuda_bf16.h>
#include <mma.h>
#include <cstdint>

using namespace nvcuda;

#define T_TOK  2048
#define H_DIM  1024
#define N_EXP  16
#define I_DIM  512
#define SI_DIM 1024
#define TOPK   4
#define RTOT   (T_TOK * TOPK)            // 8192 assignments
#define RCAP   (RTOT + N_EXP * 128)      // padded capacity (experts aligned to 128)

typedef __nv_bfloat16 bf16;

// ---------------- scratch (__device__ globals; no allocation allowed) ----------------
__device__ float g_topk_w[RTOT];
__device__ int   g_topk_idx[RTOT];
__device__ int   g_counts[N_EXP];
__device__ int   g_offsets[N_EXP];
__device__ int   g_cursor[N_EXP];
__device__ int   g_perm[RCAP];
__device__ float g_ya[(size_t)RTOT * H_DIM];

// pre-split bf16 hi/lo copies (split once per launch, reused by all GEMM tiles)
__device__ bf16 g_xh [(size_t)T_TOK * H_DIM],        g_xl [(size_t)T_TOK * H_DIM];
__device__ bf16 g_egh[(size_t)N_EXP * H_DIM * I_DIM], g_egl[(size_t)N_EXP * H_DIM * I_DIM];
__device__ bf16 g_euh[(size_t)N_EXP * H_DIM * I_DIM], g_eul[(size_t)N_EXP * H_DIM * I_DIM];
__device__ bf16 g_edh[(size_t)N_EXP * I_DIM * H_DIM], g_edl[(size_t)N_EXP * I_DIM * H_DIM];
__device__ bf16 g_sgh[(size_t)H_DIM * SI_DIM],        g_sgl[(size_t)H_DIM * SI_DIM];
__device__ bf16 g_suh[(size_t)H_DIM * SI_DIM],        g_sul[(size_t)H_DIM * SI_DIM];
__device__ bf16 g_sdh[(size_t)SI_DIM * H_DIM],        g_sdl[(size_t)SI_DIM * H_DIM];
__device__ bf16 g_acth[(size_t)RCAP * I_DIM],         g_actl[(size_t)RCAP * I_DIM];
__device__ bf16 g_shh [(size_t)T_TOK * SI_DIM],       g_shl [(size_t)T_TOK * SI_DIM];

// ---------------- helpers ----------------
__device__ __forceinline__ void split4(float4 v, uint2& hi, uint2& lo) {
    __nv_bfloat162 h0 = __floats2bfloat162_rn(v.x, v.y);
    __nv_bfloat162 h1 = __floats2bfloat162_rn(v.z, v.w);
    float2 f0 = __bfloat1622float2(h0);
    float2 f1 = __bfloat1622float2(h1);
    __nv_bfloat162 l0 = __floats2bfloat162_rn(v.x - f0.x, v.y - f0.y);
    __nv_bfloat162 l1 = __floats2bfloat162_rn(v.z - f1.x, v.w - f1.y);
    hi.x = *(uint32_t*)&h0; hi.y = *(uint32_t*)&h1;
    lo.x = *(uint32_t*)&l0; lo.y = *(uint32_t*)&l1;
}

#define CP16(dst, src) asm volatile("cp.async.cg.shared.global [%0], [%1], 16;" :: "r"(dst), "l"(src))
#define CP_COMMIT()    asm volatile("cp.async.commit_group;")
#define CP_WAIT1()     asm volatile("cp.async.wait_group 1;")

typedef wmma::fragment<wmma::matrix_a, 16, 16, 16, bf16, wmma::row_major> FragA;
typedef wmma::fragment<wmma::matrix_b, 16, 16, 16, bf16, wmma::row_major> FragB;
typedef wmma::fragment<wmma::accumulator, 16, 16, 16, float> FragC;

// ---------------- small kernels ----------------
__global__ void k_init() {
    int i = threadIdx.x;
    if (i < N_EXP) { g_counts[i] = 0; g_cursor[i] = 0; }
}

__global__ void k_split(const float4* __restrict__ src, uint2* __restrict__ h,
                        uint2* __restrict__ l, int n4) {
    int i = blockIdx.x * 256 + threadIdx.x;
    if (i >= n4) return;
    uint2 hh, ll; split4(src[i], hh, ll);
    h[i] = hh; l[i] = ll;
}

__global__ void k_gate(const float* __restrict__ x, const float* __restrict__ gw) {
    __shared__ float sx[H_DIM];
    __shared__ float ssc[N_EXP];
    int t = blockIdx.x;
    const float* xr = x + (size_t)t * H_DIM;
    for (int i = threadIdx.x; i < H_DIM / 4; i += 128)
        ((float4*)sx)[i] = ((const float4*)xr)[i];
    __syncthreads();

    int warp = threadIdx.x >> 5, lane = threadIdx.x & 31;
    for (int e = warp; e < N_EXP; e += 4) {
        const float* w = gw + (size_t)e * H_DIM;
        float s = 0.f;
        for (int k = lane; k < H_DIM; k += 32) s += sx[k] * w[k];
        #pragma unroll
        for (int o = 16; o; o >>= 1) s += __shfl_xor_sync(0xffffffff, s, o);
        if (lane == 0) ssc[e] = 1.f / (1.f + expf(-s));
    }
    __syncthreads();

    if (threadIdx.x == 0) {
        float sc[N_EXP];
        #pragma unroll
        for (int e = 0; e < N_EXP; e++) sc[e] = ssc[e];
        int idx[TOPK]; float wv[TOPK]; float sum = 0.f;
        #pragma unroll
        for (int k = 0; k < TOPK; k++) {
            int bi = 0; float bv = -1e30f;
            #pragma unroll
            for (int e = 0; e < N_EXP; e++)
                if (sc[e] > bv) { bv = sc[e]; bi = e; }
            idx[k] = bi; wv[k] = bv; sc[bi] = -1e31f; sum += bv;
        }
        float inv = 1.f / (sum + 1e-20f);
        #pragma unroll
        for (int k = 0; k < TOPK; k++) {
            g_topk_idx[t * TOPK + k] = idx[k];
            g_topk_w[t * TOPK + k]   = wv[k] * inv;
            atomicAdd(&g_counts[idx[k]], 1);
        }
    }
}

__global__ void k_offsets() {
    int s = 0;
    for (int e = 0; e < N_EXP; e++) {
        g_offsets[e] = s;
        s += (g_counts[e] + 127) & ~127;
    }
}

__global__ void k_scatter() {
    int t = blockIdx.x * 256 + threadIdx.x;
    if (t >= T_TOK) return;
    #pragma unroll
    for (int k = 0; k < TOPK; k++) {
        int e = g_topk_idx[t * TOPK + k];
        int pos = atomicAdd(&g_cursor[e], 1);
        g_perm[g_offsets[e] + pos] = t * TOPK + k;
    }
}

// ---------------- SwiGLU GEMM (bf16x3, cp.async 2-stage) ----------------
// Out (hi/lo bf16) = split( silu(A@Wg) * (A@Wu) );  A gathered per expert if GATHER
template<bool GATHER, int LDW>
__global__ __launch_bounds__(256) void k_swiglu(
    const bf16* __restrict__ Xh, const bf16* __restrict__ Xl,
    const bf16* __restrict__ Wgh, const bf16* __restrict__ Wgl,
    const bf16* __restrict__ Wuh, const bf16* __restrict__ Wul,
    bf16* __restrict__ Oh, bf16* __restrict__ Ol)
{
    constexpr int BM = 128, BN = 64, BK = 32;
    constexpr int LA = 40, LB = 72;
    constexpr int SZA = BM * LA * 2;               // 10240 B per A stream
    constexpr int SZB = BK * LB * 2;               // 4608 B per B stream
    constexpr int STG = 2 * SZA + 4 * SZB;         // 38912 B per stage
    constexpr int NT  = H_DIM / BK;                // 32 tiles

    extern __shared__ char sm[];
    __shared__ int sTok[BM];

    int nb = blockIdx.x, rb = blockIdx.y, e = blockIdx.z;
    int base = 0, cnt = T_TOK;
    if (GATHER) { base = g_offsets[e]; cnt = g_counts[e]; }
    int row0 = rb * BM;
    if (row0 >= cnt) return;
    int n0 = nb * BN;

    size_t woff = GATHER ? (size_t)e * H_DIM * I_DIM : 0;

    int tid = threadIdx.x;
    if (tid < BM) {
        int local = row0 + tid;
        sTok[tid] = GATHER ? ((local < cnt) ? (g_perm[base + local] >> 2) : 0) : local;
    }
    __syncthreads();

    // per-thread cp.async source pointers
    int r0 = tid >> 2, ac = (tid & 3) * 8;               // A: rows r0, r0+64
    int br = tid >> 3, bc = (tid & 7) * 8;               // B: row br
    const bf16* a0h = Xh + (size_t)sTok[r0]      * H_DIM + ac;
    const bf16* a0l = Xl + (size_t)sTok[r0]      * H_DIM + ac;
    const bf16* a1h = Xh + (size_t)sTok[r0 + 64] * H_DIM + ac;
    const bf16* a1l = Xl + (size_t)sTok[r0 + 64] * H_DIM + ac;
    const bf16* pgh = Wgh + woff + (size_t)br * LDW + n0 + bc;
    const bf16* pgl = Wgl + woff + (size_t)br * LDW + n0 + bc;
    const bf16* puh = Wuh + woff + (size_t)br * LDW + n0 + bc;
    const bf16* pul = Wul + woff + (size_t)br * LDW + n0 + bc;

    uint32_t smb = (uint32_t)__cvta_generic_to_shared(sm);
    uint32_t dA0 = smb + (r0 * LA + ac) * 2;
    uint32_t dA1 = smb + ((r0 + 64) * LA + ac) * 2;
    uint32_t dB  = smb + 2 * SZA + (br * LB + bc) * 2;

    #define SW_ISSUE(s, k0)  {                                               \
        uint32_t o = (s) * STG;                                              \
        CP16(dA0 + o,        a0h + (k0));                                    \
        CP16(dA0 + o + SZA,  a0l + (k0));                                    \
        CP16(dA1 + o,        a1h + (k0));                                    \
        CP16(dA1 + o + SZA,  a1l + (k0));                                    \
        size_t ko = (size_t)(k0) * LDW;                                      \
        CP16(dB + o,           pgh + ko);                                    \
        CP16(dB + o + SZB,     pgl + ko);                                    \
        CP16(dB + o + 2 * SZB, puh + ko);                                    \
        CP16(dB + o + 3 * SZB, pul + ko); }

    FragC accG[2][2], accU[2][2];
    #pragma unroll
    for (int i = 0; i < 2; i++)
        #pragma unroll
        for (int j = 0; j < 2; j++) {
            wmma::fill_fragment(accG[i][j], 0.f);
            wmma::fill_fragment(accU[i][j], 0.f);
        }

    int warp = tid >> 5;
    int rowOff = (warp >> 1) * 32, colOff = (warp & 1) * 32;

    SW_ISSUE(0, 0); CP_COMMIT();

    for (int t = 0; t < NT; t++) {
        int k1 = (t + 1) * BK;
        if (k1 < H_DIM) SW_ISSUE((t + 1) & 1, k1);
        CP_COMMIT();
        CP_WAIT1();
        __syncthreads();

        int s = t & 1;
        bf16* sAh  = (bf16*)(sm + s * STG);
        bf16* sAl  = sAh + BM * LA;
        bf16* sBgh = (bf16*)(sm + s * STG + 2 * SZA);
        bf16* sBgl = sBgh + BK * LB;
        bf16* sBuh = sBgh + 2 * BK * LB;
        bf16* sBul = sBgh + 3 * BK * LB;

        #pragma unroll
        for (int kk = 0; kk < BK; kk += 16) {
            FragA fah[2], fal[2];
            FragB fgh[2], fgl[2], fuh[2], ful[2];
            #pragma unroll
            for (int i = 0; i < 2; i++) {
                wmma::load_matrix_sync(fah[i], sAh + (rowOff + 16 * i) * LA + kk, LA);
                wmma::load_matrix_sync(fal[i], sAl + (rowOff + 16 * i) * LA + kk, LA);
            }
            #pragma unroll
            for (int j = 0; j < 2; j++) {
                wmma::load_matrix_sync(fgh[j], sBgh + kk * LB + colOff + 16 * j, LB);
                wmma::load_matrix_sync(fgl[j], sBgl + kk * LB + colOff + 16 * j, LB);
                wmma::load_matrix_sync(fuh[j], sBuh + kk * LB + colOff + 16 * j, LB);
                wmma::load_matrix_sync(ful[j], sBul + kk * LB + colOff + 16 * j, LB);
            }
            #pragma unroll
            for (int i = 0; i < 2; i++)
                #pragma unroll
                for (int j = 0; j < 2; j++) {
                    wmma::mma_sync(accG[i][j], fah[i], fgh[j], accG[i][j]);
                    wmma::mma_sync(accG[i][j], fah[i], fgl[j], accG[i][j]);
                    wmma::mma_sync(accG[i][j], fal[i], fgh[j], accG[i][j]);
                    wmma::mma_sync(accU[i][j], fah[i], fuh[j], accU[i][j]);
                    wmma::mma_sync(accU[i][j], fah[i], ful[j], accU[i][j]);
                    wmma::mma_sync(accU[i][j], fal[i], fuh[j], accU[i][j]);
                }
        }
        __syncthreads();
    }

    // Epilogue: silu(g)*u, stage fp32 in smem, write bf16 hi/lo (padded layout safe)
    float (*Ep)[BN + 4] = (float(*)[BN + 4])sm;
    #pragma unroll
    for (int i = 0; i < 2; i++)
        #pragma unroll
        for (int j = 0; j < 2; j++) {
            #pragma unroll
            for (int s2 = 0; s2 < accG[i][j].num_elements; s2++) {
                float g = accG[i][j].x[s2];
                float u = accU[i][j].x[s2];
                accG[i][j].x[s2] = g * u / (1.f + __expf(-g));
            }
            wmma::store_matrix_sync(&Ep[rowOff + 16 * i][colOff + 16 * j],
                                    accG[i][j], BN + 4, wmma::mem_row_major);
        }
    __syncthreads();
    size_t orow0 = (size_t)(GATHER ? (base + row0) : row0);
    #pragma unroll
    for (int i = 0; i < 8; i++) {
        int lin = tid + i * 256;
        int r = lin >> 4, c4 = lin & 15;
        uint2 h, l; split4(*(float4*)&Ep[r][c4 * 4], h, l);
        size_t off = (orow0 + r) * LDW + n0 + c4 * 4;
        *(uint2*)(Oh + off) = h;
        *(uint2*)(Ol + off) = l;
    }
    #undef SW_ISSUE
}

// ---------------- down projection GEMM (bf16x3, cp.async 2-stage) ----------------
template<bool SCATTER, int LDA, int KDIM>
__global__ __launch_bounds__(256) void k_down(
    const bf16* __restrict__ Ah, const bf16* __restrict__ Al,
    const bf16* __restrict__ Wh, const bf16* __restrict__ Wl,
    float* __restrict__ OutP)
{
    constexpr int BM = 128, BN = 64, BK = 32;
    constexpr int LA = 40, LB = 72;
    constexpr int SZA = BM * LA * 2;               // 10240
    constexpr int SZB = BK * LB * 2;               // 4608
    constexpr int STG = 2 * SZA + 2 * SZB;         // 29696
    constexpr int NT  = KDIM / BK;

    extern __shared__ char sm[];

    int nb = blockIdx.x, rb = blockIdx.y, e = blockIdx.z;
    int base = 0, cnt = T_TOK;
    if (SCATTER) { base = g_offsets[e]; cnt = g_counts[e]; }
    int row0 = rb * BM;
    if (row0 >= cnt) return;
    int n0 = nb * BN;

    size_t woff = SCATTER ? (size_t)e * I_DIM * H_DIM : 0;

    int tid = threadIdx.x;
    int warp = tid >> 5;
    int rowOff = (warp >> 1) * 32, colOff = (warp & 1) * 32;

    int r0 = tid >> 2, ac = (tid & 3) * 8;
    int br = tid >> 3, bc = (tid & 7) * 8;
    const bf16* a0h = Ah + (size_t)(base + row0 + r0)      * LDA + ac;
    const bf16* a0l = Al + (size_t)(base + row0 + r0)      * LDA + ac;
    const bf16* a1h = Ah + (size_t)(base + row0 + r0 + 64) * LDA + ac;
    const bf16* a1l = Al + (size_t)(base + row0 + r0 + 64) * LDA + ac;
    const bf16* pbh = Wh + woff + (size_t)br * H_DIM + n0 + bc;
    const bf16* pbl = Wl + woff + (size_t)br * H_DIM + n0 + bc;

    uint32_t smb = (uint32_t)__cvta_generic_to_shared(sm);
    uint32_t dA0 = smb + (r0 * LA + ac) * 2;
    uint32_t dA1 = smb + ((r0 + 64) * LA + ac) * 2;
    uint32_t dB  = smb + 2 * SZA + (br * LB + bc) * 2;

    #define DN_ISSUE(s, k0)  {                                               \
        uint32_t o = (s) * STG;                                              \
        CP16(dA0 + o,        a0h + (k0));                                    \
        CP16(dA0 + o + SZA,  a0l + (k0));                                    \
        CP16(dA1 + o,        a1h + (k0));                                    \
        CP16(dA1 + o + SZA,  a1l + (k0));                                    \
        size_t ko = (size_t)(k0) * H_DIM;                                    \
        CP16(dB + o,       pbh + ko);                                        \
        CP16(dB + o + SZB, pbl + ko); }

    FragC acc[2][2];
    #pragma unroll
    for (int i = 0; i < 2; i++)
        #pragma unroll
        for (int j = 0; j < 2; j++) wmma::fill_fragment(acc[i][j], 0.f);

    DN_ISSUE(0, 0); CP_COMMIT();

    for (int t = 0; t < NT; t++) {
        int k1 = (t + 1) * BK;
        if (k1 < KDIM) DN_ISSUE((t + 1) & 1, k1);
        CP_COMMIT();
        CP_WAIT1();
        __syncthreads();

        int s = t & 1;
        bf16* sAh = (bf16*)(sm + s * STG);
        bf16* sAl = sAh + BM * LA;
        bf16* sBh = (bf16*)(sm + s * STG + 2 * SZA);
        bf16* sBl = sBh + BK * LB;

        #pragma unroll
        for (int kk = 0; kk < BK; kk += 16) {
            FragA fah[2], fal[2];
            FragB fbh[2], fbl[2];
            #pragma unroll
            for (int i = 0; i < 2; i++) {
                wmma::load_matrix_sync(fah[i], sAh + (rowOff + 16 * i) * LA + kk, LA);
                wmma::load_matrix_sync(fal[i], sAl + (rowOff + 16 * i) * LA + kk, LA);
            }
            #pragma unroll
            for (int j = 0; j < 2; j++) {
                wmma::load_matrix_sync(fbh[j], sBh + kk * LB + colOff + 16 * j, LB);
                wmma::load_matrix_sync(fbl[j], sBl + kk * LB + colOff + 16 * j, LB);
            }
            #pragma unroll
            for (int i = 0; i < 2; i++)
                #pragma unroll
                for (int j = 0; j < 2; j++) {
                    wmma::mma_sync(acc[i][j], fah[i], fbh[j], acc[i][j]);
                    wmma::mma_sync(acc[i][j], fah[i], fbl[j], acc[i][j]);
                    wmma::mma_sync(acc[i][j], fal[i], fbh[j], acc[i][j]);
                }
        }
        __syncthreads();
    }

    // Epilogue: stage fp32 in smem, then gated scatter / direct write
    float (*Ep)[BN + 4] = (float(*)[BN + 4])sm;
    #pragma unroll
    for (int i = 0; i < 2; i++)
        #pragma unroll
        for (int j = 0; j < 2; j++)
            wmma::store_matrix_sync(&Ep[rowOff + 16 * i][colOff + 16 * j],
                                    acc[i][j], BN + 4, wmma::mem_row_major);
    __syncthreads();
    #pragma unroll
    for (int i = 0; i < 8; i++) {
        int lin = tid + i * 256;
        int r = lin >> 4, c4 = lin & 15;
        int local = row0 + r;
        if (SCATTER) {
            if (local < cnt) {
                int a = g_perm[base + local];
                *(float4*)(g_ya + (size_t)a * H_DIM + n0 + c4 * 4) = *(float4*)&Ep[r][c4 * 4];
            }
        } else {
            *(float4*)(OutP + (size_t)local * H_DIM + n0 + c4 * 4) = *(float4*)&Ep[r][c4 * 4];
        }
    }
    #undef DN_ISSUE
}

// out[t] = shared_out[t] + sum_k w[t,k] * ya[t*4+k]
__global__ void k_combine(float* __restrict__ Out) {
    int lin = blockIdx.x * 256 + threadIdx.x;
    int t  = lin >> 8;
    int c4 = lin & 255;
    float4 acc = ((float4*)Out)[lin];
    #pragma unroll
    for (int k = 0; k < TOPK; k++) {
        float wv = g_topk_w[t * TOPK + k];
        float4 v = *(const float4*)(g_ya + (size_t)(t * TOPK + k) * H_DIM + c4 * 4);
        acc.x += wv * v.x; acc.y += wv * v.y; acc.z += wv * v.z; acc.w += wv * v.w;
    }
    ((float4*)Out)[lin] = acc;
}

// ---------------- launch ----------------
static bf16* symaddr(const void* sym) {
    void* p = nullptr;
    cudaGetSymbolAddress(&p, sym);
    return (bf16*)p;
}

extern "C" void kernel_launch(void* const* d_in, const int* in_sizes, int n_in,
                              void* d_out, int out_size)
{
    const float* x  = (const float*)d_in[0];
    const float* gw = (const float*)d_in[1];
    const float* eg = (const float*)d_in[2];
    const float* eu = (const float*)d_in[3];
    const float* ed = (const float*)d_in[4];
    const float* sg = (const float*)d_in[5];
    const float* su = (const float*)d_in[6];
    const float* sd = (const float*)d_in[7];
    float* out = (float*)d_out;

    bf16 *xh  = symaddr(g_xh),  *xl  = symaddr(g_xl);
    bf16 *egh = symaddr(g_egh), *egl = symaddr(g_egl);
    bf16 *euh = symaddr(g_euh), *eul = symaddr(g_eul);
    bf16 *edh = symaddr(g_edh), *edl = symaddr(g_edl);
    bf16 *sgh = symaddr(g_sgh), *sgl = symaddr(g_sgl);
    bf16 *suh = symaddr(g_suh), *sul = symaddr(g_sul);
    bf16 *sdh = symaddr(g_sdh), *sdl = symaddr(g_sdl);
    bf16 *ath = symaddr(g_acth), *atl = symaddr(g_actl);
    bf16 *shh = symaddr(g_shh), *shl = symaddr(g_shl);

    constexpr int SMEM_SW = 2 * 38912;   // 77824
    constexpr int SMEM_DN = 2 * 29696;   // 59392
    cudaFuncSetAttribute(k_swiglu<true,  I_DIM >, cudaFuncAttributeMaxDynamicSharedMemorySize, SMEM_SW);
    cudaFuncSetAttribute(k_swiglu<false, SI_DIM>, cudaFuncAttributeMaxDynamicSharedMemorySize, SMEM_SW);
    cudaFuncSetAttribute(k_down<true,  I_DIM,  I_DIM >, cudaFuncAttributeMaxDynamicSharedMemorySize, SMEM_DN);
    cudaFuncSetAttribute(k_down<false, SI_DIM, SI_DIM>, cudaFuncAttributeMaxDynamicSharedMemorySize, SMEM_DN);

    // routing
    k_init<<<1, 32>>>();
    k_gate<<<T_TOK, 128>>>(x, gw);
    k_offsets<<<1, 1>>>();
    k_scatter<<<T_TOK / 256, 256>>>();

    // pre-split x + weights into bf16 hi/lo
    auto split = [](const float* s, bf16* h, bf16* l, size_t n) {
        int n4 = (int)(n / 4);
        k_split<<<(n4 + 255) / 256, 256>>>((const float4*)s, (uint2*)h, (uint2*)l, n4);
    };
    split(x,  xh,  xl,  (size_t)T_TOK * H_DIM);
    split(eg, egh, egl, (size_t)N_EXP * H_DIM * I_DIM);
    split(eu, euh, eul, (size_t)N_EXP * H_DIM * I_DIM);
    split(ed, edh, edl, (size_t)N_EXP * I_DIM * H_DIM);
    split(sg, sgh, sgl, (size_t)H_DIM * SI_DIM);
    split(su, suh, sul, (size_t)H_DIM * SI_DIM);
    split(sd, sdh, sdl, (size_t)SI_DIM * H_DIM);

    // routed SwiGLU -> g_act hi/lo
    k_swiglu<true, I_DIM><<<dim3(I_DIM / 64, 16, N_EXP), 256, SMEM_SW>>>(
        xh, xl, egh, egl, euh, eul, ath, atl);
    // shared SwiGLU -> g_sh hi/lo
    k_swiglu<false, SI_DIM><<<dim3(SI_DIM / 64, T_TOK / 128, 1), 256, SMEM_SW>>>(
        xh, xl, sgh, sgl, suh, sul, shh, shl);

    // routed down -> scatter rows into g_ya
    k_down<true, I_DIM, I_DIM><<<dim3(H_DIM / 64, 16, N_EXP), 256, SMEM_DN>>>(
        ath, atl, edh, edl, nullptr);
    // shared down -> writes d_out (covers every element)
    k_down<false, SI_DIM, SI_DIM><<<dim3(H_DIM / 64, T_TOK / 128, 1), 256, SMEM_DN>>>(
        shh, shl, sdh, sdl, out);

    k_combine<<<(T_TOK * H_DIM / 4) / 256, 256>>>(out);
}

// round 10
// speedup vs baseline: 1.7375x; 1.7375x over previous
#include <cuda_runtime.h>
#include <cuda_fp16.h>
#include <mma.h>
#include <cstdint>

using namespace nvcuda;

#define T_TOK  2048
#define H_DIM  1024
#define N_EXP  16
#define I_DIM  512
#define SI_DIM 1024
#define TOPK   4
#define RTOT   (T_TOK * TOPK)
#define RCAP   (RTOT + N_EXP * 128)

typedef __half h16;

// ---------------- scratch ----------------
__device__ float g_topk_w[RTOT];
__device__ int   g_topk_idx[RTOT];
__device__ int   g_counts[N_EXP];
__device__ int   g_offsets[N_EXP];
__device__ int   g_cursor[N_EXP];
__device__ int   g_perm[RCAP];
__device__ float g_ya[(size_t)RTOT * H_DIM];

// fp16 copies: x/act single-stream, weights hi+lo
__device__ h16 g_xh [(size_t)T_TOK * H_DIM];
__device__ h16 g_egh[(size_t)N_EXP * H_DIM * I_DIM], g_egl[(size_t)N_EXP * H_DIM * I_DIM];
__device__ h16 g_euh[(size_t)N_EXP * H_DIM * I_DIM], g_eul[(size_t)N_EXP * H_DIM * I_DIM];
__device__ h16 g_edh[(size_t)N_EXP * I_DIM * H_DIM], g_edl[(size_t)N_EXP * I_DIM * H_DIM];
__device__ h16 g_sgh[(size_t)H_DIM * SI_DIM],        g_sgl[(size_t)H_DIM * SI_DIM];
__device__ h16 g_suh[(size_t)H_DIM * SI_DIM],        g_sul[(size_t)H_DIM * SI_DIM];
__device__ h16 g_sdh[(size_t)SI_DIM * H_DIM],        g_sdl[(size_t)SI_DIM * H_DIM];
__device__ h16 g_act[(size_t)RCAP * I_DIM];
__device__ h16 g_sha[(size_t)T_TOK * SI_DIM];

// ---------------- helpers ----------------
__device__ __forceinline__ void split4h(float4 v, uint2& hi, uint2& lo) {
    __half2 h0 = __floats2half2_rn(v.x, v.y);
    __half2 h1 = __floats2half2_rn(v.z, v.w);
    float2 f0 = __half22float2(h0);
    float2 f1 = __half22float2(h1);
    __half2 l0 = __floats2half2_rn(v.x - f0.x, v.y - f0.y);
    __half2 l1 = __floats2half2_rn(v.z - f1.x, v.w - f1.y);
    hi.x = *(uint32_t*)&h0; hi.y = *(uint32_t*)&h1;
    lo.x = *(uint32_t*)&l0; lo.y = *(uint32_t*)&l1;
}
__device__ __forceinline__ uint2 cvt4h(float4 v) {
    __half2 h0 = __floats2half2_rn(v.x, v.y);
    __half2 h1 = __floats2half2_rn(v.z, v.w);
    uint2 r; r.x = *(uint32_t*)&h0; r.y = *(uint32_t*)&h1;
    return r;
}

#define CP16(dst, src) asm volatile("cp.async.cg.shared.global [%0], [%1], 16;" :: "r"(dst), "l"(src))
#define CP_COMMIT()    asm volatile("cp.async.commit_group;")
#define CP_WAIT1()     asm volatile("cp.async.wait_group 1;")

typedef wmma::fragment<wmma::matrix_a, 16, 16, 16, h16, wmma::row_major> FragA;
typedef wmma::fragment<wmma::matrix_b, 16, 16, 16, h16, wmma::row_major> FragB;
typedef wmma::fragment<wmma::accumulator, 16, 16, 16, float> FragC;

// ---------------- small kernels ----------------
__global__ void k_init() {
    int i = threadIdx.x;
    if (i < N_EXP) { g_counts[i] = 0; g_cursor[i] = 0; }
}

__global__ void k_split_hl(const float4* __restrict__ src, uint2* __restrict__ h,
                           uint2* __restrict__ l, int n4) {
    int i = blockIdx.x * 256 + threadIdx.x;
    if (i >= n4) return;
    uint2 hh, ll; split4h(src[i], hh, ll);
    h[i] = hh; l[i] = ll;
}

__global__ void k_split_h(const float4* __restrict__ src, uint2* __restrict__ h, int n4) {
    int i = blockIdx.x * 256 + threadIdx.x;
    if (i >= n4) return;
    h[i] = cvt4h(src[i]);
}

__global__ void k_gate(const float* __restrict__ x, const float* __restrict__ gw) {
    __shared__ float sx[H_DIM];
    __shared__ float ssc[N_EXP];
    int t = blockIdx.x;
    const float* xr = x + (size_t)t * H_DIM;
    for (int i = threadIdx.x; i < H_DIM / 4; i += 128)
        ((float4*)sx)[i] = ((const float4*)xr)[i];
    __syncthreads();

    int warp = threadIdx.x >> 5, lane = threadIdx.x & 31;
    for (int e = warp; e < N_EXP; e += 4) {
        const float* w = gw + (size_t)e * H_DIM;
        float s = 0.f;
        for (int k = lane; k < H_DIM; k += 32) s += sx[k] * w[k];
        #pragma unroll
        for (int o = 16; o; o >>= 1) s += __shfl_xor_sync(0xffffffff, s, o);
        if (lane == 0) ssc[e] = 1.f / (1.f + expf(-s));
    }
    __syncthreads();

    if (threadIdx.x == 0) {
        float sc[N_EXP];
        #pragma unroll
        for (int e = 0; e < N_EXP; e++) sc[e] = ssc[e];
        int idx[TOPK]; float wv[TOPK]; float sum = 0.f;
        #pragma unroll
        for (int k = 0; k < TOPK; k++) {
            int bi = 0; float bv = -1e30f;
            #pragma unroll
            for (int e = 0; e < N_EXP; e++)
                if (sc[e] > bv) { bv = sc[e]; bi = e; }
            idx[k] = bi; wv[k] = bv; sc[bi] = -1e31f; sum += bv;
        }
        float inv = 1.f / (sum + 1e-20f);
        #pragma unroll
        for (int k = 0; k < TOPK; k++) {
            g_topk_idx[t * TOPK + k] = idx[k];
            g_topk_w[t * TOPK + k]   = wv[k] * inv;
            atomicAdd(&g_counts[idx[k]], 1);
        }
    }
}

__global__ void k_offsets() {
    int s = 0;
    for (int e = 0; e < N_EXP; e++) {
        g_offsets[e] = s;
        s += (g_counts[e] + 127) & ~127;
    }
}

__global__ void k_scatter() {
    int t = blockIdx.x * 256 + threadIdx.x;
    if (t >= T_TOK) return;
    #pragma unroll
    for (int k = 0; k < TOPK; k++) {
        int e = g_topk_idx[t * TOPK + k];
        int pos = atomicAdd(&g_cursor[e], 1);
        g_perm[g_offsets[e] + pos] = t * TOPK + k;
    }
}

// ---------------- SwiGLU GEMM (fp16 2-term, cp.async 2-stage) ----------------
// act_fp16 = fp16( silu(A@(Wgh+Wgl)) * (A@(Wuh+Wul)) ), A = fp16 single stream
template<bool GATHER, int LDW>
__global__ __launch_bounds__(256) void k_swiglu(
    const h16* __restrict__ Xh,
    const h16* __restrict__ Wgh, const h16* __restrict__ Wgl,
    const h16* __restrict__ Wuh, const h16* __restrict__ Wul,
    h16* __restrict__ Oh)
{
    constexpr int BM = 128, BN = 64, BK = 32;
    constexpr int LA = 40, LB = 72;
    constexpr int SZA = BM * LA * 2;               // 10240
    constexpr int SZB = BK * LB * 2;               // 4608
    constexpr int STG = SZA + 4 * SZB;             // 28672 per stage
    constexpr int NT  = H_DIM / BK;                // 32

    extern __shared__ char sm[];
    __shared__ int sTok[BM];

    int nb = blockIdx.x, rb = blockIdx.y, e = blockIdx.z;
    int base = 0, cnt = T_TOK;
    if (GATHER) { base = g_offsets[e]; cnt = g_counts[e]; }
    int row0 = rb * BM;
    if (row0 >= cnt) return;
    int n0 = nb * BN;
    size_t woff = GATHER ? (size_t)e * H_DIM * I_DIM : 0;

    int tid = threadIdx.x;
    if (tid < BM) {
        int local = row0 + tid;
        sTok[tid] = GATHER ? ((local < cnt) ? (g_perm[base + local] >> 2) : 0) : local;
    }
    __syncthreads();

    int r0 = tid >> 2, ac = (tid & 3) * 8;        // A: rows r0, r0+64
    int br = tid >> 3, bc = (tid & 7) * 8;        // B: row br
    const h16* a0 = Xh + (size_t)sTok[r0]      * H_DIM + ac;
    const h16* a1 = Xh + (size_t)sTok[r0 + 64] * H_DIM + ac;
    const h16* pgh = Wgh + woff + (size_t)br * LDW + n0 + bc;
    const h16* pgl = Wgl + woff + (size_t)br * LDW + n0 + bc;
    const h16* puh = Wuh + woff + (size_t)br * LDW + n0 + bc;
    const h16* pul = Wul + woff + (size_t)br * LDW + n0 + bc;

    uint32_t smb = (uint32_t)__cvta_generic_to_shared(sm);
    uint32_t dA0 = smb + (r0 * LA + ac) * 2;
    uint32_t dA1 = smb + ((r0 + 64) * LA + ac) * 2;
    uint32_t dB  = smb + SZA + (br * LB + bc) * 2;

    #define SW_ISSUE(s, k0)  {                                               \
        uint32_t o = (s) * STG;                                              \
        CP16(dA0 + o, a0 + (k0));                                            \
        CP16(dA1 + o, a1 + (k0));                                            \
        size_t ko = (size_t)(k0) * LDW;                                      \
        CP16(dB + o,           pgh + ko);                                    \
        CP16(dB + o + SZB,     pgl + ko);                                    \
        CP16(dB + o + 2 * SZB, puh + ko);                                    \
        CP16(dB + o + 3 * SZB, pul + ko); }

    FragC accG[2][2], accU[2][2];
    #pragma unroll
    for (int i = 0; i < 2; i++)
        #pragma unroll
        for (int j = 0; j < 2; j++) {
            wmma::fill_fragment(accG[i][j], 0.f);
            wmma::fill_fragment(accU[i][j], 0.f);
        }

    int warp = tid >> 5;
    int rowOff = (warp >> 1) * 32, colOff = (warp & 1) * 32;

    SW_ISSUE(0, 0); CP_COMMIT();

    for (int t = 0; t < NT; t++) {
        int k1 = (t + 1) * BK;
        if (k1 < H_DIM) SW_ISSUE((t + 1) & 1, k1);
        CP_COMMIT();
        CP_WAIT1();
        __syncthreads();

        int s = t & 1;
        h16* sA   = (h16*)(sm + s * STG);
        h16* sBgh = (h16*)(sm + s * STG + SZA);
        h16* sBgl = sBgh + BK * LB;
        h16* sBuh = sBgh + 2 * BK * LB;
        h16* sBul = sBgh + 3 * BK * LB;

        #pragma unroll
        for (int kk = 0; kk < BK; kk += 16) {
            FragA fa[2];
            FragB fgh[2], fgl[2], fuh[2], ful[2];
            #pragma unroll
            for (int i = 0; i < 2; i++)
                wmma::load_matrix_sync(fa[i], sA + (rowOff + 16 * i) * LA + kk, LA);
            #pragma unroll
            for (int j = 0; j < 2; j++) {
                wmma::load_matrix_sync(fgh[j], sBgh + kk * LB + colOff + 16 * j, LB);
                wmma::load_matrix_sync(fgl[j], sBgl + kk * LB + colOff + 16 * j, LB);
                wmma::load_matrix_sync(fuh[j], sBuh + kk * LB + colOff + 16 * j, LB);
                wmma::load_matrix_sync(ful[j], sBul + kk * LB + colOff + 16 * j, LB);
            }
            #pragma unroll
            for (int i = 0; i < 2; i++)
                #pragma unroll
                for (int j = 0; j < 2; j++) {
                    wmma::mma_sync(accG[i][j], fa[i], fgh[j], accG[i][j]);
                    wmma::mma_sync(accG[i][j], fa[i], fgl[j], accG[i][j]);
                    wmma::mma_sync(accU[i][j], fa[i], fuh[j], accU[i][j]);
                    wmma::mma_sync(accU[i][j], fa[i], ful[j], accU[i][j]);
                }
        }
        __syncthreads();
    }

    // Epilogue: silu(g)*u -> fp16 (padded layout, full-tile store safe)
    float (*Ep)[BN + 4] = (float(*)[BN + 4])sm;
    #pragma unroll
    for (int i = 0; i < 2; i++)
        #pragma unroll
        for (int j = 0; j < 2; j++) {
            #pragma unroll
            for (int s2 = 0; s2 < accG[i][j].num_elements; s2++) {
                float g = accG[i][j].x[s2];
                float u = accU[i][j].x[s2];
                accG[i][j].x[s2] = g * u / (1.f + __expf(-g));
            }
            wmma::store_matrix_sync(&Ep[rowOff + 16 * i][colOff + 16 * j],
                                    accG[i][j], BN + 4, wmma::mem_row_major);
        }
    __syncthreads();
    size_t orow0 = (size_t)(GATHER ? (base + row0) : row0);
    #pragma unroll
    for (int i = 0; i < 8; i++) {
        int lin = tid + i * 256;
        int r = lin >> 4, c4 = lin & 15;
        uint2 h = cvt4h(*(float4*)&Ep[r][c4 * 4]);
        *(uint2*)(Oh + (orow0 + r) * LDW + n0 + c4 * 4) = h;
    }
    #undef SW_ISSUE
}

// ---------------- down projection GEMM (fp16 2-term, cp.async 2-stage) ----------------
template<bool SCATTER, int LDA, int KDIM>
__global__ __launch_bounds__(256) void k_down(
    const h16* __restrict__ Ah,
    const h16* __restrict__ Wh, const h16* __restrict__ Wl,
    float* __restrict__ OutP)
{
    constexpr int BM = 128, BN = 64, BK = 32;
    constexpr int LA = 40, LB = 72;
    constexpr int SZA = BM * LA * 2;               // 10240
    constexpr int SZB = BK * LB * 2;               // 4608
    constexpr int STG = SZA + 2 * SZB;             // 19456
    constexpr int NT  = KDIM / BK;

    extern __shared__ char sm[];

    int nb = blockIdx.x, rb = blockIdx.y, e = blockIdx.z;
    int base = 0, cnt = T_TOK;
    if (SCATTER) { base = g_offsets[e]; cnt = g_counts[e]; }
    int row0 = rb * BM;
    if (row0 >= cnt) return;
    int n0 = nb * BN;
    size_t woff = SCATTER ? (size_t)e * I_DIM * H_DIM : 0;

    int tid = threadIdx.x;
    int warp = tid >> 5;
    int rowOff = (warp >> 1) * 32, colOff = (warp & 1) * 32;

    int r0 = tid >> 2, ac = (tid & 3) * 8;
    int br = tid >> 3, bc = (tid & 7) * 8;
    const h16* a0 = Ah + (size_t)(base + row0 + r0)      * LDA + ac;
    const h16* a1 = Ah + (size_t)(base + row0 + r0 + 64) * LDA + ac;
    const h16* pbh = Wh + woff + (size_t)br * H_DIM + n0 + bc;
    const h16* pbl = Wl + woff + (size_t)br * H_DIM + n0 + bc;

    uint32_t smb = (uint32_t)__cvta_generic_to_shared(sm);
    uint32_t dA0 = smb + (r0 * LA + ac) * 2;
    uint32_t dA1 = smb + ((r0 + 64) * LA + ac) * 2;
    uint32_t dB  = smb + SZA + (br * LB + bc) * 2;

    #define DN_ISSUE(s, k0)  {                                               \
        uint32_t o = (s) * STG;                                              \
        CP16(dA0 + o, a0 + (k0));                                            \
        CP16(dA1 + o, a1 + (k0));                                            \
        size_t ko = (size_t)(k0) * H_DIM;                                    \
        CP16(dB + o,       pbh + ko);                                        \
        CP16(dB + o + SZB, pbl + ko); }

    FragC acc[2][2];
    #pragma unroll
    for (int i = 0; i < 2; i++)
        #pragma unroll
        for (int j = 0; j < 2; j++) wmma::fill_fragment(acc[i][j], 0.f);

    DN_ISSUE(0, 0); CP_COMMIT();

    for (int t = 0; t < NT; t++) {
        int k1 = (t + 1) * BK;
        if (k1 < KDIM) DN_ISSUE((t + 1) & 1, k1);
        CP_COMMIT();
        CP_WAIT1();
        __syncthreads();

        int s = t & 1;
        h16* sA  = (h16*)(sm + s * STG);
        h16* sBh = (h16*)(sm + s * STG + SZA);
        h16* sBl = sBh + BK * LB;

        #pragma unroll
        for (int kk = 0; kk < BK; kk += 16) {
            FragA fa[2];
            FragB fbh[2], fbl[2];
            #pragma unroll
            for (int i = 0; i < 2; i++)
                wmma::load_matrix_sync(fa[i], sA + (rowOff + 16 * i) * LA + kk, LA);
            #pragma unroll
            for (int j = 0; j < 2; j++) {
                wmma::load_matrix_sync(fbh[j], sBh + kk * LB + colOff + 16 * j, LB);
                wmma::load_matrix_sync(fbl[j], sBl + kk * LB + colOff + 16 * j, LB);
            }
            #pragma unroll
            for (int i = 0; i < 2; i++)
                #pragma unroll
                for (int j = 0; j < 2; j++) {
                    wmma::mma_sync(acc[i][j], fa[i], fbh[j], acc[i][j]);
                    wmma::mma_sync(acc[i][j], fa[i], fbl[j], acc[i][j]);
                }
        }
        __syncthreads();
    }

    // Epilogue: stage fp32 in smem, gated scatter / direct write
    float (*Ep)[BN + 4] = (float(*)[BN + 4])sm;
    #pragma unroll
    for (int i = 0; i < 2; i++)
        #pragma unroll
        for (int j = 0; j < 2; j++)
            wmma::store_matrix_sync(&Ep[rowOff + 16 * i][colOff + 16 * j],
                                    acc[i][j], BN + 4, wmma::mem_row_major);
    __syncthreads();
    #pragma unroll
    for (int i = 0; i < 8; i++) {
        int lin = tid + i * 256;
        int r = lin >> 4, c4 = lin & 15;
        int local = row0 + r;
        if (SCATTER) {
            if (local < cnt) {
                int a = g_perm[base + local];
                *(float4*)(g_ya + (size_t)a * H_DIM + n0 + c4 * 4) = *(float4*)&Ep[r][c4 * 4];
            }
        } else {
            *(float4*)(OutP + (size_t)local * H_DIM + n0 + c4 * 4) = *(float4*)&Ep[r][c4 * 4];
        }
    }
    #undef DN_ISSUE
}

// out[t] = shared_out[t] + sum_k w[t,k] * ya[t*4+k]
__global__ void k_combine(float* __restrict__ Out) {
    int lin = blockIdx.x * 256 + threadIdx.x;
    int t  = lin >> 8;
    int c4 = lin & 255;
    float4 acc = ((float4*)Out)[lin];
    #pragma unroll
    for (int k = 0; k < TOPK; k++) {
        float wv = g_topk_w[t * TOPK + k];
        float4 v = *(const float4*)(g_ya + (size_t)(t * TOPK + k) * H_DIM + c4 * 4);
        acc.x += wv * v.x; acc.y += wv * v.y; acc.z += wv * v.z; acc.w += wv * v.w;
    }
    ((float4*)Out)[lin] = acc;
}

// ---------------- launch ----------------
static h16* symaddr(const void* sym) {
    void* p = nullptr;
    cudaGetSymbolAddress(&p, sym);
    return (h16*)p;
}

extern "C" void kernel_launch(void* const* d_in, const int* in_sizes, int n_in,
                              void* d_out, int out_size)
{
    const float* x  = (const float*)d_in[0];
    const float* gw = (const float*)d_in[1];
    const float* eg = (const float*)d_in[2];
    const float* eu = (const float*)d_in[3];
    const float* ed = (const float*)d_in[4];
    const float* sg = (const float*)d_in[5];
    const float* su = (const float*)d_in[6];
    const float* sd = (const float*)d_in[7];
    float* out = (float*)d_out;

    h16 *xh  = symaddr(g_xh);
    h16 *egh = symaddr(g_egh), *egl = symaddr(g_egl);
    h16 *euh = symaddr(g_euh), *eul = symaddr(g_eul);
    h16 *edh = symaddr(g_edh), *edl = symaddr(g_edl);
    h16 *sgh = symaddr(g_sgh), *sgl = symaddr(g_sgl);
    h16 *suh = symaddr(g_suh), *sul = symaddr(g_sul);
    h16 *sdh = symaddr(g_sdh), *sdl = symaddr(g_sdl);
    h16 *act = symaddr(g_act), *sha = symaddr(g_sha);

    constexpr int SMEM_SW = 2 * 28672;   // 57344
    constexpr int SMEM_DN = 2 * 19456;   // 38912
    cudaFuncSetAttribute(k_swiglu<true,  I_DIM >, cudaFuncAttributeMaxDynamicSharedMemorySize, SMEM_SW);
    cudaFuncSetAttribute(k_swiglu<false, SI_DIM>, cudaFuncAttributeMaxDynamicSharedMemorySize, SMEM_SW);
    cudaFuncSetAttribute(k_down<true,  I_DIM,  I_DIM >, cudaFuncAttributeMaxDynamicSharedMemorySize, SMEM_DN);
    cudaFuncSetAttribute(k_down<false, SI_DIM, SI_DIM>, cudaFuncAttributeMaxDynamicSharedMemorySize, SMEM_DN);

    // routing
    k_init<<<1, 32>>>();
    k_gate<<<T_TOK, 128>>>(x, gw);
    k_offsets<<<1, 1>>>();
    k_scatter<<<T_TOK / 256, 256>>>();

    // fp16 conversions: weights hi+lo, x hi-only
    auto splhl = [](const float* s, h16* h, h16* l, size_t n) {
        int n4 = (int)(n / 4);
        k_split_hl<<<(n4 + 255) / 256, 256>>>((const float4*)s, (uint2*)h, (uint2*)l, n4);
    };
    {
        int n4 = (int)((size_t)T_TOK * H_DIM / 4);
        k_split_h<<<(n4 + 255) / 256, 256>>>((const float4*)x, (uint2*)xh, n4);
    }
    splhl(eg, egh, egl, (size_t)N_EXP * H_DIM * I_DIM);
    splhl(eu, euh, eul, (size_t)N_EXP * H_DIM * I_DIM);
    splhl(ed, edh, edl, (size_t)N_EXP * I_DIM * H_DIM);
    splhl(sg, sgh, sgl, (size_t)H_DIM * SI_DIM);
    splhl(su, suh, sul, (size_t)H_DIM * SI_DIM);
    splhl(sd, sdh, sdl, (size_t)SI_DIM * H_DIM);

    // routed SwiGLU -> g_act (fp16)
    k_swiglu<true, I_DIM><<<dim3(I_DIM / 64, 16, N_EXP), 256, SMEM_SW>>>(
        xh, egh, egl, euh, eul, act);
    // shared SwiGLU -> g_sha (fp16)
    k_swiglu<false, SI_DIM><<<dim3(SI_DIM / 64, T_TOK / 128, 1), 256, SMEM_SW>>>(
        xh, sgh, sgl, suh, sul, sha);

    // routed down -> scatter rows into g_ya
    k_down<true, I_DIM, I_DIM><<<dim3(H_DIM / 64, 16, N_EXP), 256, SMEM_DN>>>(
        act, edh, edl, nullptr);
    // shared down -> writes d_out (covers every element)
    k_down<false, SI_DIM, SI_DIM><<<dim3(H_DIM / 64, T_TOK / 128, 1), 256, SMEM_DN>>>(
        sha, sdh, sdl, out);

    k_combine<<<(T_TOK * H_DIM / 4) / 256, 256>>>(out);
}

// round 14
// speedup vs baseline: 2.2066x; 1.2700x over previous
#include <cuda_runtime.h>
#include <cuda_fp16.h>
#include <mma.h>
#include <cstdint>

using namespace nvcuda;

#define T_TOK  2048
#define H_DIM  1024
#define N_EXP  16
#define I_DIM  512
#define SI_DIM 1024
#define TOPK   4
#define RTOT   (T_TOK * TOPK)
#define RCAP   (RTOT + N_EXP * 128)

typedef __half h16;

// ---------------- scratch ----------------
__device__ float g_topk_w[RTOT];
__device__ int   g_topk_idx[RTOT];
__device__ int   g_counts[N_EXP];
__device__ int   g_offsets[N_EXP];
__device__ int   g_cursor[N_EXP];
__device__ int   g_perm[RCAP];
__device__ float g_ya[(size_t)RTOT * H_DIM];

// fp16 copies (single stream everywhere)
__device__ h16 g_xh [(size_t)T_TOK * H_DIM];
__device__ h16 g_egh[(size_t)N_EXP * H_DIM * I_DIM];
__device__ h16 g_euh[(size_t)N_EXP * H_DIM * I_DIM];
__device__ h16 g_edh[(size_t)N_EXP * I_DIM * H_DIM];
__device__ h16 g_sgh[(size_t)H_DIM * SI_DIM];
__device__ h16 g_suh[(size_t)H_DIM * SI_DIM];
__device__ h16 g_sdh[(size_t)SI_DIM * H_DIM];
__device__ h16 g_act[(size_t)RCAP * I_DIM];
__device__ h16 g_sha[(size_t)T_TOK * SI_DIM];

// ---------------- helpers ----------------
__device__ __forceinline__ uint2 cvt4h(float4 v) {
    __half2 h0 = __floats2half2_rn(v.x, v.y);
    __half2 h1 = __floats2half2_rn(v.z, v.w);
    uint2 r; r.x = *(uint32_t*)&h0; r.y = *(uint32_t*)&h1;
    return r;
}

#define CP16(dst, src) asm volatile("cp.async.cg.shared.global [%0], [%1], 16;" :: "r"(dst), "l"(src))
#define CP_COMMIT()    asm volatile("cp.async.commit_group;")
#define CP_WAIT1()     asm volatile("cp.async.wait_group 1;")

typedef wmma::fragment<wmma::matrix_a, 16, 16, 16, h16, wmma::row_major> FragA;
typedef wmma::fragment<wmma::matrix_b, 16, 16, 16, h16, wmma::row_major> FragB;
typedef wmma::fragment<wmma::accumulator, 16, 16, 16, float> FragC;

// ---------------- small kernels ----------------
__global__ void k_init() {
    int i = threadIdx.x;
    if (i < N_EXP) { g_counts[i] = 0; g_cursor[i] = 0; }
}

__global__ void k_split_h(const float4* __restrict__ src, uint2* __restrict__ h, int n4) {
    int i = blockIdx.x * 256 + threadIdx.x;
    if (i >= n4) return;
    h[i] = cvt4h(src[i]);
}

__global__ void k_gate(const float* __restrict__ x, const float* __restrict__ gw) {
    __shared__ float sx[H_DIM];
    __shared__ float ssc[N_EXP];
    int t = blockIdx.x;
    const float* xr = x + (size_t)t * H_DIM;
    for (int i = threadIdx.x; i < H_DIM / 4; i += 128)
        ((float4*)sx)[i] = ((const float4*)xr)[i];
    __syncthreads();

    int warp = threadIdx.x >> 5, lane = threadIdx.x & 31;
    for (int e = warp; e < N_EXP; e += 4) {
        const float* w = gw + (size_t)e * H_DIM;
        float s = 0.f;
        for (int k = lane; k < H_DIM; k += 32) s += sx[k] * w[k];
        #pragma unroll
        for (int o = 16; o; o >>= 1) s += __shfl_xor_sync(0xffffffff, s, o);
        if (lane == 0) ssc[e] = 1.f / (1.f + expf(-s));
    }
    __syncthreads();

    if (threadIdx.x == 0) {
        float sc[N_EXP];
        #pragma unroll
        for (int e = 0; e < N_EXP; e++) sc[e] = ssc[e];
        int idx[TOPK]; float wv[TOPK]; float sum = 0.f;
        #pragma unroll
        for (int k = 0; k < TOPK; k++) {
            int bi = 0; float bv = -1e30f;
            #pragma unroll
            for (int e = 0; e < N_EXP; e++)
                if (sc[e] > bv) { bv = sc[e]; bi = e; }
            idx[k] = bi; wv[k] = bv; sc[bi] = -1e31f; sum += bv;
        }
        float inv = 1.f / (sum + 1e-20f);
        #pragma unroll
        for (int k = 0; k < TOPK; k++) {
            g_topk_idx[t * TOPK + k] = idx[k];
            g_topk_w[t * TOPK + k]   = wv[k] * inv;
            atomicAdd(&g_counts[idx[k]], 1);
        }
    }
}

__global__ void k_offsets() {
    int s = 0;
    for (int e = 0; e < N_EXP; e++) {
        g_offsets[e] = s;
        s += (g_counts[e] + 127) & ~127;
    }
}

__global__ void k_scatter() {
    int t = blockIdx.x * 256 + threadIdx.x;
    if (t >= T_TOK) return;
    #pragma unroll
    for (int k = 0; k < TOPK; k++) {
        int e = g_topk_idx[t * TOPK + k];
        int pos = atomicAdd(&g_cursor[e], 1);
        g_perm[g_offsets[e] + pos] = t * TOPK + k;
    }
}

// ---------------- SwiGLU GEMM (fp16, cp.async 2-stage) ----------------
// act_fp16 = fp16( silu(A@Wg) * (A@Wu) )
template<bool GATHER, int LDW>
__global__ __launch_bounds__(256) void k_swiglu(
    const h16* __restrict__ Xh,
    const h16* __restrict__ Wg, const h16* __restrict__ Wu,
    h16* __restrict__ Oh)
{
    constexpr int BM = 128, BN = 64, BK = 32;
    constexpr int LA = 40, LB = 72;
    constexpr int SZA = BM * LA * 2;               // 10240
    constexpr int SZB = BK * LB * 2;               // 4608
    constexpr int STG = SZA + 2 * SZB;             // 19456 per stage
    constexpr int NT  = H_DIM / BK;                // 32

    extern __shared__ char sm[];
    __shared__ int sTok[BM];

    int nb = blockIdx.x, rb = blockIdx.y, e = blockIdx.z;
    int base = 0, cnt = T_TOK;
    if (GATHER) { base = g_offsets[e]; cnt = g_counts[e]; }
    int row0 = rb * BM;
    if (row0 >= cnt) return;
    int n0 = nb * BN;
    size_t woff = GATHER ? (size_t)e * H_DIM * I_DIM : 0;

    int tid = threadIdx.x;
    if (tid < BM) {
        int local = row0 + tid;
        sTok[tid] = GATHER ? ((local < cnt) ? (g_perm[base + local] >> 2) : 0) : local;
    }
    __syncthreads();

    int r0 = tid >> 2, ac = (tid & 3) * 8;        // A: rows r0, r0+64
    int br = tid >> 3, bc = (tid & 7) * 8;        // B: row br
    const h16* a0 = Xh + (size_t)sTok[r0]      * H_DIM + ac;
    const h16* a1 = Xh + (size_t)sTok[r0 + 64] * H_DIM + ac;
    const h16* pg = Wg + woff + (size_t)br * LDW + n0 + bc;
    const h16* pu = Wu + woff + (size_t)br * LDW + n0 + bc;

    uint32_t smb = (uint32_t)__cvta_generic_to_shared(sm);
    uint32_t dA0 = smb + (r0 * LA + ac) * 2;
    uint32_t dA1 = smb + ((r0 + 64) * LA + ac) * 2;
    uint32_t dB  = smb + SZA + (br * LB + bc) * 2;

    #define SW_ISSUE(s, k0)  {                                               \
        uint32_t o = (s) * STG;                                              \
        CP16(dA0 + o, a0 + (k0));                                            \
        CP16(dA1 + o, a1 + (k0));                                            \
        size_t ko = (size_t)(k0) * LDW;                                      \
        CP16(dB + o,       pg + ko);                                         \
        CP16(dB + o + SZB, pu + ko); }

    FragC accG[2][2], accU[2][2];
    #pragma unroll
    for (int i = 0; i < 2; i++)
        #pragma unroll
        for (int j = 0; j < 2; j++) {
            wmma::fill_fragment(accG[i][j], 0.f);
            wmma::fill_fragment(accU[i][j], 0.f);
        }

    int warp = tid >> 5;
    int rowOff = (warp >> 1) * 32, colOff = (warp & 1) * 32;

    SW_ISSUE(0, 0); CP_COMMIT();

    for (int t = 0; t < NT; t++) {
        int k1 = (t + 1) * BK;
        if (k1 < H_DIM) SW_ISSUE((t + 1) & 1, k1);
        CP_COMMIT();
        CP_WAIT1();
        __syncthreads();

        int s = t & 1;
        h16* sA  = (h16*)(sm + s * STG);
        h16* sBg = (h16*)(sm + s * STG + SZA);
        h16* sBu = sBg + BK * LB;

        #pragma unroll
        for (int kk = 0; kk < BK; kk += 16) {
            FragA fa[2];
            FragB fg[2], fu[2];
            #pragma unroll
            for (int i = 0; i < 2; i++)
                wmma::load_matrix_sync(fa[i], sA + (rowOff + 16 * i) * LA + kk, LA);
            #pragma unroll
            for (int j = 0; j < 2; j++) {
                wmma::load_matrix_sync(fg[j], sBg + kk * LB + colOff + 16 * j, LB);
                wmma::load_matrix_sync(fu[j], sBu + kk * LB + colOff + 16 * j, LB);
            }
            #pragma unroll
            for (int i = 0; i < 2; i++)
                #pragma unroll
                for (int j = 0; j < 2; j++) {
                    wmma::mma_sync(accG[i][j], fa[i], fg[j], accG[i][j]);
                    wmma::mma_sync(accU[i][j], fa[i], fu[j], accU[i][j]);
                }
        }
        __syncthreads();
    }

    // Epilogue: silu(g)*u -> fp16 (padded layout, full-tile store safe)
    float (*Ep)[BN + 4] = (float(*)[BN + 4])sm;
    #pragma unroll
    for (int i = 0; i < 2; i++)
        #pragma unroll
        for (int j = 0; j < 2; j++) {
            #pragma unroll
            for (int s2 = 0; s2 < accG[i][j].num_elements; s2++) {
                float g = accG[i][j].x[s2];
                float u = accU[i][j].x[s2];
                accG[i][j].x[s2] = g * u / (1.f + __expf(-g));
            }
            wmma::store_matrix_sync(&Ep[rowOff + 16 * i][colOff + 16 * j],
                                    accG[i][j], BN + 4, wmma::mem_row_major);
        }
    __syncthreads();
    size_t orow0 = (size_t)(GATHER ? (base + row0) : row0);
    #pragma unroll
    for (int i = 0; i < 8; i++) {
        int lin = tid + i * 256;
        int r = lin >> 4, c4 = lin & 15;
        uint2 h = cvt4h(*(float4*)&Ep[r][c4 * 4]);
        *(uint2*)(Oh + (orow0 + r) * LDW + n0 + c4 * 4) = h;
    }
    #undef SW_ISSUE
}

// ---------------- down projection GEMM (fp16, cp.async 2-stage) ----------------
template<bool SCATTER, int LDA, int KDIM>
__global__ __launch_bounds__(256) void k_down(
    const h16* __restrict__ Ah,
    const h16* __restrict__ Wh,
    float* __restrict__ OutP)
{
    constexpr int BM = 128, BN = 64, BK = 32;
    constexpr int LA = 40, LB = 72;
    constexpr int SZA = BM * LA * 2;               // 10240
    constexpr int SZB = BK * LB * 2;               // 4608
    constexpr int STG = SZA + SZB;                 // 14848 per stage
    constexpr int NT  = KDIM / BK;

    extern __shared__ char sm[];

    int nb = blockIdx.x, rb = blockIdx.y, e = blockIdx.z;
    int base = 0, cnt = T_TOK;
    if (SCATTER) { base = g_offsets[e]; cnt = g_counts[e]; }
    int row0 = rb * BM;
    if (row0 >= cnt) return;
    int n0 = nb * BN;
    size_t woff = SCATTER ? (size_t)e * I_DIM * H_DIM : 0;

    int tid = threadIdx.x;
    int warp = tid >> 5;
    int rowOff = (warp >> 1) * 32, colOff = (warp & 1) * 32;

    int r0 = tid >> 2, ac = (tid & 3) * 8;
    int br = tid >> 3, bc = (tid & 7) * 8;
    const h16* a0 = Ah + (size_t)(base + row0 + r0)      * LDA + ac;
    const h16* a1 = Ah + (size_t)(base + row0 + r0 + 64) * LDA + ac;
    const h16* pb = Wh + woff + (size_t)br * H_DIM + n0 + bc;

    uint32_t smb = (uint32_t)__cvta_generic_to_shared(sm);
    uint32_t dA0 = smb + (r0 * LA + ac) * 2;
    uint32_t dA1 = smb + ((r0 + 64) * LA + ac) * 2;
    uint32_t dB  = smb + SZA + (br * LB + bc) * 2;

    #define DN_ISSUE(s, k0)  {                                               \
        uint32_t o = (s) * STG;                                              \
        CP16(dA0 + o, a0 + (k0));                                            \
        CP16(dA1 + o, a1 + (k0));                                            \
        CP16(dB + o, pb + (size_t)(k0) * H_DIM); }

    FragC acc[2][2];
    #pragma unroll
    for (int i = 0; i < 2; i++)
        #pragma unroll
        for (int j = 0; j < 2; j++) wmma::fill_fragment(acc[i][j], 0.f);

    DN_ISSUE(0, 0); CP_COMMIT();

    for (int t = 0; t < NT; t++) {
        int k1 = (t + 1) * BK;
        if (k1 < KDIM) DN_ISSUE((t + 1) & 1, k1);
        CP_COMMIT();
        CP_WAIT1();
        __syncthreads();

        int s = t & 1;
        h16* sA = (h16*)(sm + s * STG);
        h16* sB = (h16*)(sm + s * STG + SZA);

        #pragma unroll
        for (int kk = 0; kk < BK; kk += 16) {
            FragA fa[2];
            FragB fb[2];
            #pragma unroll
            for (int i = 0; i < 2; i++)
                wmma::load_matrix_sync(fa[i], sA + (rowOff + 16 * i) * LA + kk, LA);
            #pragma unroll
            for (int j = 0; j < 2; j++)
                wmma::load_matrix_sync(fb[j], sB + kk * LB + colOff + 16 * j, LB);
            #pragma unroll
            for (int i = 0; i < 2; i++)
                #pragma unroll
                for (int j = 0; j < 2; j++)
                    wmma::mma_sync(acc[i][j], fa[i], fb[j], acc[i][j]);
        }
        __syncthreads();
    }

    // Epilogue: stage fp32 in smem, gated scatter / direct write
    float (*Ep)[BN + 4] = (float(*)[BN + 4])sm;
    #pragma unroll
    for (int i = 0; i < 2; i++)
        #pragma unroll
        for (int j = 0; j < 2; j++)
            wmma::store_matrix_sync(&Ep[rowOff + 16 * i][colOff + 16 * j],
                                    acc[i][j], BN + 4, wmma::mem_row_major);
    __syncthreads();
    #pragma unroll
    for (int i = 0; i < 8; i++) {
        int lin = tid + i * 256;
        int r = lin >> 4, c4 = lin & 15;
        int local = row0 + r;
        if (SCATTER) {
            if (local < cnt) {
                int a = g_perm[base + local];
                *(float4*)(g_ya + (size_t)a * H_DIM + n0 + c4 * 4) = *(float4*)&Ep[r][c4 * 4];
            }
        } else {
            *(float4*)(OutP + (size_t)local * H_DIM + n0 + c4 * 4) = *(float4*)&Ep[r][c4 * 4];
        }
    }
    #undef DN_ISSUE
}

// out[t] = shared_out[t] + sum_k w[t,k] * ya[t*4+k]
__global__ void k_combine(float* __restrict__ Out) {
    int lin = blockIdx.x * 256 + threadIdx.x;
    int t  = lin >> 8;
    int c4 = lin & 255;
    float4 acc = ((float4*)Out)[lin];
    #pragma unroll
    for (int k = 0; k < TOPK; k++) {
        float wv = g_topk_w[t * TOPK + k];
        float4 v = *(const float4*)(g_ya + (size_t)(t * TOPK + k) * H_DIM + c4 * 4);
        acc.x += wv * v.x; acc.y += wv * v.y; acc.z += wv * v.z; acc.w += wv * v.w;
    }
    ((float4*)Out)[lin] = acc;
}

// ---------------- launch ----------------
static h16* symaddr(const void* sym) {
    void* p = nullptr;
    cudaGetSymbolAddress(&p, sym);
    return (h16*)p;
}

extern "C" void kernel_launch(void* const* d_in, const int* in_sizes, int n_in,
                              void* d_out, int out_size)
{
    const float* x  = (const float*)d_in[0];
    const float* gw = (const float*)d_in[1];
    const float* eg = (const float*)d_in[2];
    const float* eu = (const float*)d_in[3];
    const float* ed = (const float*)d_in[4];
    const float* sg = (const float*)d_in[5];
    const float* su = (const float*)d_in[6];
    const float* sd = (const float*)d_in[7];
    float* out = (float*)d_out;

    h16 *xh  = symaddr(g_xh);
    h16 *egh = symaddr(g_egh), *euh = symaddr(g_euh), *edh = symaddr(g_edh);
    h16 *sgh = symaddr(g_sgh), *suh = symaddr(g_suh), *sdh = symaddr(g_sdh);
    h16 *act = symaddr(g_act), *sha = symaddr(g_sha);

    constexpr int SMEM_SW = 2 * 19456;            // 38912 (>= 34816 epilogue)
    constexpr int SMEM_DN = 34816;                // max(2*14848, epilogue 34816)
    cudaFuncSetAttribute(k_swiglu<true,  I_DIM >, cudaFuncAttributeMaxDynamicSharedMemorySize, SMEM_SW);
    cudaFuncSetAttribute(k_swiglu<false, SI_DIM>, cudaFuncAttributeMaxDynamicSharedMemorySize, SMEM_SW);
    cudaFuncSetAttribute(k_down<true,  I_DIM,  I_DIM >, cudaFuncAttributeMaxDynamicSharedMemorySize, SMEM_DN);
    cudaFuncSetAttribute(k_down<false, SI_DIM, SI_DIM>, cudaFuncAttributeMaxDynamicSharedMemorySize, SMEM_DN);

    // routing
    k_init<<<1, 32>>>();
    k_gate<<<T_TOK, 128>>>(x, gw);
    k_offsets<<<1, 1>>>();
    k_scatter<<<T_TOK / 256, 256>>>();

    // fp16 conversions
    auto cvt = [](const float* s, h16* h, size_t n) {
        int n4 = (int)(n / 4);
        k_split_h<<<(n4 + 255) / 256, 256>>>((const float4*)s, (uint2*)h, n4);
    };
    cvt(x,  xh,  (size_t)T_TOK * H_DIM);
    cvt(eg, egh, (size_t)N_EXP * H_DIM * I_DIM);
    cvt(eu, euh, (size_t)N_EXP * H_DIM * I_DIM);
    cvt(ed, edh, (size_t)N_EXP * I_DIM * H_DIM);
    cvt(sg, sgh, (size_t)H_DIM * SI_DIM);
    cvt(su, suh, (size_t)H_DIM * SI_DIM);
    cvt(sd, sdh, (size_t)SI_DIM * H_DIM);

    // routed SwiGLU -> g_act (fp16)
    k_swiglu<true, I_DIM><<<dim3(I_DIM / 64, 16, N_EXP), 256, SMEM_SW>>>(
        xh, egh, euh, act);
    // shared SwiGLU -> g_sha (fp16)
    k_swiglu<false, SI_DIM><<<dim3(SI_DIM / 64, T_TOK / 128, 1), 256, SMEM_SW>>>(
        xh, sgh, suh, sha);

    // routed down -> scatter rows into g_ya
    k_down<true, I_DIM, I_DIM><<<dim3(H_DIM / 64, 16, N_EXP), 256, SMEM_DN>>>(
        act, edh, nullptr);
    // shared down -> writes d_out (covers every element)
    k_down<false, SI_DIM, SI_DIM><<<dim3(H_DIM / 64, T_TOK / 128, 1), 256, SMEM_DN>>>(
        sha, sdh, out);

    k_combine<<<(T_TOK * H_DIM / 4) / 256, 256>>>(out);
}

// round 15
// speedup vs baseline: 2.5167x; 1.1405x over previous
#include <cuda_runtime.h>
#include <cuda_fp16.h>
#include <mma.h>
#include <cstdint>

using namespace nvcuda;

#define T_TOK  2048
#define H_DIM  1024
#define N_EXP  16
#define I_DIM  512
#define SI_DIM 1024
#define TOPK   4
#define RTOT   (T_TOK * TOPK)
#define RCAP   (RTOT + N_EXP * 128)

typedef __half h16;

// ---------------- scratch ----------------
__device__ float g_topk_w[RTOT];
__device__ int   g_topk_idx[RTOT];
__device__ int   g_counts[N_EXP];
__device__ int   g_offsets[N_EXP];
__device__ int   g_cursor[N_EXP];
__device__ int   g_perm[RCAP];
__device__ float g_ya[(size_t)RTOT * H_DIM];

__device__ h16 g_xh [(size_t)T_TOK * H_DIM];
__device__ h16 g_egh[(size_t)N_EXP * H_DIM * I_DIM];
__device__ h16 g_euh[(size_t)N_EXP * H_DIM * I_DIM];
__device__ h16 g_edh[(size_t)N_EXP * I_DIM * H_DIM];
__device__ h16 g_sgh[(size_t)H_DIM * SI_DIM];
__device__ h16 g_suh[(size_t)H_DIM * SI_DIM];
__device__ h16 g_sdh[(size_t)SI_DIM * H_DIM];
__device__ h16 g_act[(size_t)RCAP * I_DIM];
__device__ h16 g_sha[(size_t)T_TOK * SI_DIM];

// ---------------- helpers ----------------
__device__ __forceinline__ uint2 cvt4h(float4 v) {
    __half2 h0 = __floats2half2_rn(v.x, v.y);
    __half2 h1 = __floats2half2_rn(v.z, v.w);
    uint2 r; r.x = *(uint32_t*)&h0; r.y = *(uint32_t*)&h1;
    return r;
}

#define CP16(dst, src) asm volatile("cp.async.cg.shared.global [%0], [%1], 16;" :: "r"(dst), "l"(src))
#define CP_COMMIT()    asm volatile("cp.async.commit_group;")

typedef wmma::fragment<wmma::matrix_a, 16, 16, 16, h16, wmma::row_major> FragA;
typedef wmma::fragment<wmma::matrix_b, 16, 16, 16, h16, wmma::row_major> FragB;
typedef wmma::fragment<wmma::accumulator, 16, 16, 16, float> FragC;

// ---------------- small kernels ----------------
__global__ void k_init() {
    int i = threadIdx.x;
    if (i < N_EXP) { g_counts[i] = 0; g_cursor[i] = 0; }
}

struct CvtArgs {
    const float4* s[7];
    uint2*        d[7];
    int           n4[7];
};

__global__ void k_cvt7(CvtArgs a) {
    int seg = blockIdx.y;
    int n4 = a.n4[seg];
    int i = blockIdx.x * 256 + threadIdx.x;
    if (i >= n4) return;
    a.d[seg][i] = cvt4h(a.s[seg][i]);
}

__global__ void k_gate(const float* __restrict__ x, const float* __restrict__ gw) {
    __shared__ float sx[H_DIM];
    __shared__ float ssc[N_EXP];
    int t = blockIdx.x;
    const float* xr = x + (size_t)t * H_DIM;
    for (int i = threadIdx.x; i < H_DIM / 4; i += 128)
        ((float4*)sx)[i] = ((const float4*)xr)[i];
    __syncthreads();

    int warp = threadIdx.x >> 5, lane = threadIdx.x & 31;
    for (int e = warp; e < N_EXP; e += 4) {
        const float* w = gw + (size_t)e * H_DIM;
        float s = 0.f;
        for (int k = lane; k < H_DIM; k += 32) s += sx[k] * w[k];
        #pragma unroll
        for (int o = 16; o; o >>= 1) s += __shfl_xor_sync(0xffffffff, s, o);
        if (lane == 0) ssc[e] = 1.f / (1.f + expf(-s));
    }
    __syncthreads();

    if (threadIdx.x == 0) {
        float sc[N_EXP];
        #pragma unroll
        for (int e = 0; e < N_EXP; e++) sc[e] = ssc[e];
        int idx[TOPK]; float wv[TOPK]; float sum = 0.f;
        #pragma unroll
        for (int k = 0; k < TOPK; k++) {
            int bi = 0; float bv = -1e30f;
            #pragma unroll
            for (int e = 0; e < N_EXP; e++)
                if (sc[e] > bv) { bv = sc[e]; bi = e; }
            idx[k] = bi; wv[k] = bv; sc[bi] = -1e31f; sum += bv;
        }
        float inv = 1.f / (sum + 1e-20f);
        #pragma unroll
        for (int k = 0; k < TOPK; k++) {
            g_topk_idx[t * TOPK + k] = idx[k];
            g_topk_w[t * TOPK + k]   = wv[k] * inv;
            atomicAdd(&g_counts[idx[k]], 1);
        }
    }
}

__global__ void k_offsets() {
    int s = 0;
    for (int e = 0; e < N_EXP; e++) {
        g_offsets[e] = s;
        s += (g_counts[e] + 127) & ~127;
    }
}

__global__ void k_scatter() {
    int t = blockIdx.x * 256 + threadIdx.x;
    if (t >= T_TOK) return;
    #pragma unroll
    for (int k = 0; k < TOPK; k++) {
        int e = g_topk_idx[t * TOPK + k];
        int pos = atomicAdd(&g_cursor[e], 1);
        g_perm[g_offsets[e] + pos] = t * TOPK + k;
    }
}

// ---------------- SwiGLU GEMM (fp16, 512 thr, BM128 BN128 BK64, 3-stage) ----------------
template<bool GATHER, int LDW>
__global__ __launch_bounds__(512) void k_swiglu(
    const h16* __restrict__ Xh,
    const h16* __restrict__ Wg, const h16* __restrict__ Wu,
    h16* __restrict__ Oh)
{
    constexpr int BM = 128, BN = 128, BK = 64;
    constexpr int LA = 72, LB = 136;
    constexpr int SZA = BM * LA * 2;                // 18432
    constexpr int SZB = BK * LB * 2;                // 17408
    constexpr int STG = SZA + 2 * SZB;              // 53248
    constexpr int NT  = H_DIM / BK;                 // 16

    extern __shared__ char sm[];
    __shared__ int sTok[BM];

    int nb = blockIdx.x, rb = blockIdx.y, e = blockIdx.z;
    int base = 0, cnt = T_TOK;
    if (GATHER) { base = g_offsets[e]; cnt = g_counts[e]; }
    int row0 = rb * BM;
    if (row0 >= cnt) return;
    int n0 = nb * BN;
    size_t woff = GATHER ? (size_t)e * H_DIM * I_DIM : 0;

    int tid = threadIdx.x;
    if (tid < BM) {
        int local = row0 + tid;
        sTok[tid] = GATHER ? ((local < cnt) ? (g_perm[base + local] >> 2) : 0) : local;
    }
    __syncthreads();

    // load mapping: A 1024 chunks (rows r, r+64); B 1024 chunks (rows br, br+32)
    int ar = tid >> 3, ac = (tid & 7) * 8;
    int br = tid >> 4, bc = (tid & 15) * 8;
    const h16* pA0 = Xh + (size_t)sTok[ar]      * H_DIM + ac;
    const h16* pA1 = Xh + (size_t)sTok[ar + 64] * H_DIM + ac;
    const h16* pg0 = Wg + woff + (size_t)br        * LDW + n0 + bc;
    const h16* pg1 = Wg + woff + (size_t)(br + 32) * LDW + n0 + bc;
    const h16* pu0 = Wu + woff + (size_t)br        * LDW + n0 + bc;
    const h16* pu1 = Wu + woff + (size_t)(br + 32) * LDW + n0 + bc;

    uint32_t smb = (uint32_t)__cvta_generic_to_shared(sm);
    uint32_t dA0 = smb + (ar * LA + ac) * 2;
    uint32_t dA1 = smb + ((ar + 64) * LA + ac) * 2;
    uint32_t dB0 = smb + SZA + (br * LB + bc) * 2;
    uint32_t dB1 = smb + SZA + ((br + 32) * LB + bc) * 2;

    #define SW_ISSUE(s, k0)  {                                               \
        uint32_t o = (s) * STG;                                              \
        CP16(dA0 + o, pA0 + (k0));                                           \
        CP16(dA1 + o, pA1 + (k0));                                           \
        size_t ko = (size_t)(k0) * LDW;                                      \
        CP16(dB0 + o,       pg0 + ko);                                       \
        CP16(dB1 + o,       pg1 + ko);                                       \
        CP16(dB0 + o + SZB, pu0 + ko);                                       \
        CP16(dB1 + o + SZB, pu1 + ko); }

    FragC accG[2][2], accU[2][2];
    #pragma unroll
    for (int i = 0; i < 2; i++)
        #pragma unroll
        for (int j = 0; j < 2; j++) {
            wmma::fill_fragment(accG[i][j], 0.f);
            wmma::fill_fragment(accU[i][j], 0.f);
        }

    int warp = tid >> 5;                       // 16 warps: 4x4
    int rowOff = (warp >> 2) * 32, colOff = (warp & 3) * 32;

    SW_ISSUE(0, 0); CP_COMMIT();
    SW_ISSUE(1, BK); CP_COMMIT();

    for (int t = 0; t < NT; t++) {
        if (t + 2 < NT) {
            SW_ISSUE((t + 2) % 3, (t + 2) * BK); CP_COMMIT();
            asm volatile("cp.async.wait_group 2;");
        } else if (t + 1 < NT) {
            asm volatile("cp.async.wait_group 1;");
        } else {
            asm volatile("cp.async.wait_group 0;");
        }
        __syncthreads();

        int s = t % 3;
        h16* sA  = (h16*)(sm + s * STG);
        h16* sBg = (h16*)(sm + s * STG + SZA);
        h16* sBu = (h16*)(sm + s * STG + SZA + SZB);

        #pragma unroll
        for (int kk = 0; kk < BK; kk += 16) {
            FragA fa[2];
            FragB fg[2], fu[2];
            #pragma unroll
            for (int i = 0; i < 2; i++)
                wmma::load_matrix_sync(fa[i], sA + (rowOff + 16 * i) * LA + kk, LA);
            #pragma unroll
            for (int j = 0; j < 2; j++) {
                wmma::load_matrix_sync(fg[j], sBg + kk * LB + colOff + 16 * j, LB);
                wmma::load_matrix_sync(fu[j], sBu + kk * LB + colOff + 16 * j, LB);
            }
            #pragma unroll
            for (int i = 0; i < 2; i++)
                #pragma unroll
                for (int j = 0; j < 2; j++) {
                    wmma::mma_sync(accG[i][j], fa[i], fg[j], accG[i][j]);
                    wmma::mma_sync(accU[i][j], fa[i], fu[j], accU[i][j]);
                }
        }
        __syncthreads();
    }

    // Epilogue: silu(g)*u -> fp16 (padded layout, full-tile store safe)
    float (*Ep)[BN + 4] = (float(*)[BN + 4])sm;
    #pragma unroll
    for (int i = 0; i < 2; i++)
        #pragma unroll
        for (int j = 0; j < 2; j++) {
            #pragma unroll
            for (int s2 = 0; s2 < accG[i][j].num_elements; s2++) {
                float g = accG[i][j].x[s2];
                float u = accU[i][j].x[s2];
                accG[i][j].x[s2] = g * u / (1.f + __expf(-g));
            }
            wmma::store_matrix_sync(&Ep[rowOff + 16 * i][colOff + 16 * j],
                                    accG[i][j], BN + 4, wmma::mem_row_major);
        }
    __syncthreads();
    size_t orow0 = (size_t)(GATHER ? (base + row0) : row0);
    #pragma unroll
    for (int i = 0; i < 8; i++) {
        int lin = tid + i * 512;               // 128 rows x 32 float4
        int r = lin >> 5, c4 = lin & 31;
        uint2 h = cvt4h(*(float4*)&Ep[r][c4 * 4]);
        *(uint2*)(Oh + (orow0 + r) * LDW + n0 + c4 * 4) = h;
    }
    #undef SW_ISSUE
}

// ---------------- down GEMM (fp16, 512 thr, BM128 BN128 BK64, 3-stage) ----------------
template<bool SCATTER, int LDA, int KDIM>
__global__ __launch_bounds__(512) void k_down(
    const h16* __restrict__ Ah,
    const h16* __restrict__ Wh,
    float* __restrict__ OutP)
{
    constexpr int BM = 128, BN = 128, BK = 64;
    constexpr int LA = 72, LB = 136;
    constexpr int SZA = BM * LA * 2;                // 18432
    constexpr int SZB = BK * LB * 2;                // 17408
    constexpr int STG = SZA + SZB;                  // 35840
    constexpr int NT  = KDIM / BK;

    extern __shared__ char sm[];

    int nb = blockIdx.x, rb = blockIdx.y, e = blockIdx.z;
    int base = 0, cnt = T_TOK;
    if (SCATTER) { base = g_offsets[e]; cnt = g_counts[e]; }
    int row0 = rb * BM;
    if (row0 >= cnt) return;
    int n0 = nb * BN;
    size_t woff = SCATTER ? (size_t)e * I_DIM * H_DIM : 0;

    int tid = threadIdx.x;
    int warp = tid >> 5;
    int rowOff = (warp >> 2) * 32, colOff = (warp & 3) * 32;

    int ar = tid >> 3, ac = (tid & 7) * 8;
    int br = tid >> 4, bc = (tid & 15) * 8;
    const h16* pA0 = Ah + (size_t)(base + row0 + ar)      * LDA + ac;
    const h16* pA1 = Ah + (size_t)(base + row0 + ar + 64) * LDA + ac;
    const h16* pb0 = Wh + woff + (size_t)br        * H_DIM + n0 + bc;
    const h16* pb1 = Wh + woff + (size_t)(br + 32) * H_DIM + n0 + bc;

    uint32_t smb = (uint32_t)__cvta_generic_to_shared(sm);
    uint32_t dA0 = smb + (ar * LA + ac) * 2;
    uint32_t dA1 = smb + ((ar + 64) * LA + ac) * 2;
    uint32_t dB0 = smb + SZA + (br * LB + bc) * 2;
    uint32_t dB1 = smb + SZA + ((br + 32) * LB + bc) * 2;

    #define DN_ISSUE(s, k0)  {                                               \
        uint32_t o = (s) * STG;                                              \
        CP16(dA0 + o, pA0 + (k0));                                           \
        CP16(dA1 + o, pA1 + (k0));                                           \
        size_t ko = (size_t)(k0) * H_DIM;                                    \
        CP16(dB0 + o, pb0 + ko);                                             \
        CP16(dB1 + o, pb1 + ko); }

    FragC acc[2][2];
    #pragma unroll
    for (int i = 0; i < 2; i++)
        #pragma unroll
        for (int j = 0; j < 2; j++) wmma::fill_fragment(acc[i][j], 0.f);

    DN_ISSUE(0, 0); CP_COMMIT();
    DN_ISSUE(1, BK); CP_COMMIT();

    for (int t = 0; t < NT; t++) {
        if (t + 2 < NT) {
            DN_ISSUE((t + 2) % 3, (t + 2) * BK); CP_COMMIT();
            asm volatile("cp.async.wait_group 2;");
        } else if (t + 1 < NT) {
            asm volatile("cp.async.wait_group 1;");
        } else {
            asm volatile("cp.async.wait_group 0;");
        }
        __syncthreads();

        int s = t % 3;
        h16* sA = (h16*)(sm + s * STG);
        h16* sB = (h16*)(sm + s * STG + SZA);

        #pragma unroll
        for (int kk = 0; kk < BK; kk += 16) {
            FragA fa[2];
            FragB fb[2];
            #pragma unroll
            for (int i = 0; i < 2; i++)
                wmma::load_matrix_sync(fa[i], sA + (rowOff + 16 * i) * LA + kk, LA);
            #pragma unroll
            for (int j = 0; j < 2; j++)
                wmma::load_matrix_sync(fb[j], sB + kk * LB + colOff + 16 * j, LB);
            #pragma unroll
            for (int i = 0; i < 2; i++)
                #pragma unroll
                for (int j = 0; j < 2; j++)
                    wmma::mma_sync(acc[i][j], fa[i], fb[j], acc[i][j]);
        }
        __syncthreads();
    }

    // Epilogue: stage fp32 in smem, gated scatter / direct write
    float (*Ep)[BN + 4] = (float(*)[BN + 4])sm;
    #pragma unroll
    for (int i = 0; i < 2; i++)
        #pragma unroll
        for (int j = 0; j < 2; j++)
            wmma::store_matrix_sync(&Ep[rowOff + 16 * i][colOff + 16 * j],
                                    acc[i][j], BN + 4, wmma::mem_row_major);
    __syncthreads();
    #pragma unroll
    for (int i = 0; i < 8; i++) {
        int lin = tid + i * 512;               // 128 rows x 32 float4
        int r = lin >> 5, c4 = lin & 31;
        int local = row0 + r;
        if (SCATTER) {
            if (local < cnt) {
                int a = g_perm[base + local];
                *(float4*)(g_ya + (size_t)a * H_DIM + n0 + c4 * 4) = *(float4*)&Ep[r][c4 * 4];
            }
        } else {
            *(float4*)(OutP + (size_t)local * H_DIM + n0 + c4 * 4) = *(float4*)&Ep[r][c4 * 4];
        }
    }
    #undef DN_ISSUE
}

// out[t] = shared_out[t] + sum_k w[t,k] * ya[t*4+k]
__global__ void k_combine(float* __restrict__ Out) {
    int lin = blockIdx.x * 256 + threadIdx.x;
    int t  = lin >> 8;
    int c4 = lin & 255;
    float4 acc = ((float4*)Out)[lin];
    #pragma unroll
    for (int k = 0; k < TOPK; k++) {
        float wv = g_topk_w[t * TOPK + k];
        float4 v = *(const float4*)(g_ya + (size_t)(t * TOPK + k) * H_DIM + c4 * 4);
        acc.x += wv * v.x; acc.y += wv * v.y; acc.z += wv * v.z; acc.w += wv * v.w;
    }
    ((float4*)Out)[lin] = acc;
}

// ---------------- launch ----------------
static h16* symaddr(const void* sym) {
    void* p = nullptr;
    cudaGetSymbolAddress(&p, sym);
    return (h16*)p;
}

extern "C" void kernel_launch(void* const* d_in, const int* in_sizes, int n_in,
                              void* d_out, int out_size)
{
    const float* x  = (const float*)d_in[0];
    const float* gw = (const float*)d_in[1];
    const float* eg = (const float*)d_in[2];
    const float* eu = (const float*)d_in[3];
    const float* ed = (const float*)d_in[4];
    const float* sg = (const float*)d_in[5];
    const float* su = (const float*)d_in[6];
    const float* sd = (const float*)d_in[7];
    float* out = (float*)d_out;

    h16 *xh  = symaddr(g_xh);
    h16 *egh = symaddr(g_egh), *euh = symaddr(g_euh), *edh = symaddr(g_edh);
    h16 *sgh = symaddr(g_sgh), *suh = symaddr(g_suh), *sdh = symaddr(g_sdh);
    h16 *act = symaddr(g_act), *sha = symaddr(g_sha);

    constexpr int SMEM_SW = 3 * 53248;            // 159744
    constexpr int SMEM_DN = 3 * 35840;            // 107520
    cudaFuncSetAttribute(k_swiglu<true,  I_DIM >, cudaFuncAttributeMaxDynamicSharedMemorySize, SMEM_SW);
    cudaFuncSetAttribute(k_swiglu<false, SI_DIM>, cudaFuncAttributeMaxDynamicSharedMemorySize, SMEM_SW);
    cudaFuncSetAttribute(k_down<true,  I_DIM,  I_DIM >, cudaFuncAttributeMaxDynamicSharedMemorySize, SMEM_DN);
    cudaFuncSetAttribute(k_down<false, SI_DIM, SI_DIM>, cudaFuncAttributeMaxDynamicSharedMemorySize, SMEM_DN);

    // routing
    k_init<<<1, 32>>>();
    k_gate<<<T_TOK, 128>>>(x, gw);
    k_offsets<<<1, 1>>>();
    k_scatter<<<T_TOK / 256, 256>>>();

    // fused fp16 conversions (7 tensors, one launch)
    {
        CvtArgs a;
        const float* srcs[7] = {x, eg, eu, ed, sg, su, sd};
        h16*         dsts[7] = {xh, egh, euh, edh, sgh, suh, sdh};
        size_t       ns[7]   = {(size_t)T_TOK * H_DIM,
                                (size_t)N_EXP * H_DIM * I_DIM,
                                (size_t)N_EXP * H_DIM * I_DIM,
                                (size_t)N_EXP * I_DIM * H_DIM,
                                (size_t)H_DIM * SI_DIM,
                                (size_t)H_DIM * SI_DIM,
                                (size_t)SI_DIM * H_DIM};
        int maxb = 0;
        for (int i = 0; i < 7; i++) {
            a.s[i]  = (const float4*)srcs[i];
            a.d[i]  = (uint2*)dsts[i];
            a.n4[i] = (int)(ns[i] / 4);
            int b = (a.n4[i] + 255) / 256;
            if (b > maxb) maxb = b;
        }
        k_cvt7<<<dim3(maxb, 7), 256>>>(a);
    }

    // routed SwiGLU -> g_act (fp16)
    k_swiglu<true, I_DIM><<<dim3(I_DIM / 128, 16, N_EXP), 512, SMEM_SW>>>(
        xh, egh, euh, act);
    // shared SwiGLU -> g_sha (fp16)
    k_swiglu<false, SI_DIM><<<dim3(SI_DIM / 128, T_TOK / 128, 1), 512, SMEM_SW>>>(
        xh, sgh, suh, sha);

    // routed down -> scatter rows into g_ya
    k_down<true, I_DIM, I_DIM><<<dim3(H_DIM / 128, 16, N_EXP), 512, SMEM_DN>>>(
        act, edh, nullptr);
    // shared down -> writes d_out (covers every element)
    k_down<false, SI_DIM, SI_DIM><<<dim3(H_DIM / 128, T_TOK / 128, 1), 512, SMEM_DN>>>(
        sha, sdh, out);

    k_combine<<<(T_TOK * H_DIM / 4) / 256, 256>>>(out);
}

// round 17
// speedup vs baseline: 2.5295x; 1.0051x over previous
#include <cuda_runtime.h>
#include <cuda_fp16.h>
#include <mma.h>
#include <cstdint>

using namespace nvcuda;

#define T_TOK  2048
#define H_DIM  1024
#define N_EXP  16
#define I_DIM  512
#define SI_DIM 1024
#define TOPK   4
#define RTOT   (T_TOK * TOPK)
#define RCAP   (RTOT + N_EXP * 128)

typedef __half h16;

// ---------------- scratch ----------------
__device__ float g_topk_w[RTOT];
__device__ int   g_topk_idx[RTOT];
__device__ int   g_counts[N_EXP];
__device__ int   g_offsets[N_EXP];
__device__ int   g_cursor[N_EXP];
__device__ int   g_perm[RCAP];
__device__ float g_ya[(size_t)RTOT * H_DIM];

__device__ h16 g_xh [(size_t)T_TOK * H_DIM];
__device__ h16 g_egh[(size_t)N_EXP * H_DIM * I_DIM];
__device__ h16 g_euh[(size_t)N_EXP * H_DIM * I_DIM];
__device__ h16 g_edh[(size_t)N_EXP * I_DIM * H_DIM];
__device__ h16 g_sgh[(size_t)H_DIM * SI_DIM];
__device__ h16 g_suh[(size_t)H_DIM * SI_DIM];
__device__ h16 g_sdh[(size_t)SI_DIM * H_DIM];
__device__ h16 g_act[(size_t)RCAP * I_DIM];
__device__ h16 g_sha[(size_t)T_TOK * SI_DIM];

// ---------------- helpers ----------------
__device__ __forceinline__ uint2 cvt4h(float4 v) {
    __half2 h0 = __floats2half2_rn(v.x, v.y);
    __half2 h1 = __floats2half2_rn(v.z, v.w);
    uint2 r; r.x = *(uint32_t*)&h0; r.y = *(uint32_t*)&h1;
    return r;
}

#define CP16(dst, src) asm volatile("cp.async.cg.shared.global [%0], [%1], 16;" :: "r"(dst), "l"(src))
#define CP_COMMIT()    asm volatile("cp.async.commit_group;")

typedef wmma::fragment<wmma::matrix_a, 16, 16, 16, h16, wmma::row_major> FragA;
typedef wmma::fragment<wmma::matrix_b, 16, 16, 16, h16, wmma::row_major> FragB;
typedef wmma::fragment<wmma::accumulator, 16, 16, 16, float> FragC;

// ---------------- small kernels ----------------
__global__ void k_init() {
    int i = threadIdx.x;
    if (i < N_EXP) { g_counts[i] = 0; g_cursor[i] = 0; }
}

struct CvtArgs {
    const float4* s[7];
    uint2*        d[7];
    int           n4[7];
};

// Fused prep: y==0 -> MoE gate (first 2048 x-blocks); y=1..7 -> fp16 convert of tensor y-1.
__global__ void k_prep(const float* __restrict__ x, const float* __restrict__ gw, CvtArgs a) {
    if (blockIdx.y == 0) {
        int t = blockIdx.x;
        if (t >= T_TOK) return;
        __shared__ float sx[H_DIM];
        __shared__ float ssc[N_EXP];
        const float* xr = x + (size_t)t * H_DIM;
        ((float4*)sx)[threadIdx.x] = ((const float4*)xr)[threadIdx.x];   // 256 = H/4
        __syncthreads();

        int warp = threadIdx.x >> 5, lane = threadIdx.x & 31;            // 8 warps
        for (int e = warp; e < N_EXP; e += 8) {
            const float* w = gw + (size_t)e * H_DIM;
            float s = 0.f;
            for (int k = lane; k < H_DIM; k += 32) s += sx[k] * w[k];
            #pragma unroll
            for (int o = 16; o; o >>= 1) s += __shfl_xor_sync(0xffffffff, s, o);
            if (lane == 0) ssc[e] = 1.f / (1.f + expf(-s));
        }
        __syncthreads();

        if (threadIdx.x == 0) {
            float sc[N_EXP];
            #pragma unroll
            for (int e = 0; e < N_EXP; e++) sc[e] = ssc[e];
            int idx[TOPK]; float wv[TOPK]; float sum = 0.f;
            #pragma unroll
            for (int k = 0; k < TOPK; k++) {
                int bi = 0; float bv = -1e30f;
                #pragma unroll
                for (int e = 0; e < N_EXP; e++)
                    if (sc[e] > bv) { bv = sc[e]; bi = e; }
                idx[k] = bi; wv[k] = bv; sc[bi] = -1e31f; sum += bv;
            }
            float inv = 1.f / (sum + 1e-20f);
            #pragma unroll
            for (int k = 0; k < TOPK; k++) {
                g_topk_idx[t * TOPK + k] = idx[k];
                g_topk_w[t * TOPK + k]   = wv[k] * inv;
                atomicAdd(&g_counts[idx[k]], 1);
            }
        }
    } else {
        int seg = blockIdx.y - 1;
        int n4 = a.n4[seg];
        int i = blockIdx.x * 256 + threadIdx.x;
        if (i >= n4) return;
        a.d[seg][i] = cvt4h(a.s[seg][i]);
    }
}

__global__ void k_offsets() {
    int s = 0;
    for (int e = 0; e < N_EXP; e++) {
        g_offsets[e] = s;
        s += (g_counts[e] + 127) & ~127;
    }
}

__global__ void k_scatter() {
    int t = blockIdx.x * 256 + threadIdx.x;
    if (t >= T_TOK) return;
    #pragma unroll
    for (int k = 0; k < TOPK; k++) {
        int e = g_topk_idx[t * TOPK + k];
        int pos = atomicAdd(&g_cursor[e], 1);
        g_perm[g_offsets[e] + pos] = t * TOPK + k;
    }
}

// ---------------- fused SwiGLU GEMM (routed z<16, shared z==16) ----------------
// 512 thr, BM128 BN128 BK64, 3-stage cp.async
__global__ __launch_bounds__(512) void k_swiglu_f(
    const h16* __restrict__ Xh,
    const h16* __restrict__ Egh, const h16* __restrict__ Euh,
    const h16* __restrict__ Sgh, const h16* __restrict__ Suh,
    h16* __restrict__ Act, h16* __restrict__ Sha)
{
    constexpr int BM = 128, BN = 128, BK = 64;
    constexpr int LA = 72, LB = 136;
    constexpr int SZA = BM * LA * 2;                // 18432
    constexpr int SZB = BK * LB * 2;                // 17408
    constexpr int STG = SZA + 2 * SZB;              // 53248
    constexpr int NT  = H_DIM / BK;                 // 16 (K = H for both paths)

    extern __shared__ char sm[];
    __shared__ int sTok[BM];

    int nb = blockIdx.x, rb = blockIdx.y, z = blockIdx.z;
    bool routed = (z < N_EXP);

    int base, cnt, ldw;
    const h16 *Wg, *Wu;
    h16* Oh;
    if (routed) {
        if (nb >= I_DIM / BN) return;               // only 4 N-blocks
        base = g_offsets[z]; cnt = g_counts[z]; ldw = I_DIM;
        size_t woff = (size_t)z * H_DIM * I_DIM;
        Wg = Egh + woff; Wu = Euh + woff; Oh = Act;
    } else {
        base = 0; cnt = T_TOK; ldw = SI_DIM;
        Wg = Sgh; Wu = Suh; Oh = Sha;
    }
    int row0 = rb * BM;
    if (row0 >= cnt) return;
    int n0 = nb * BN;

    int tid = threadIdx.x;
    if (tid < BM) {
        int local = row0 + tid;
        sTok[tid] = routed ? ((local < cnt) ? (g_perm[base + local] >> 2) : 0) : local;
    }
    __syncthreads();

    int ar = tid >> 3, ac = (tid & 7) * 8;
    int br = tid >> 4, bc = (tid & 15) * 8;
    const h16* pA0 = Xh + (size_t)sTok[ar]      * H_DIM + ac;
    const h16* pA1 = Xh + (size_t)sTok[ar + 64] * H_DIM + ac;
    const h16* pg0 = Wg + (size_t)br        * ldw + n0 + bc;
    const h16* pg1 = Wg + (size_t)(br + 32) * ldw + n0 + bc;
    const h16* pu0 = Wu + (size_t)br        * ldw + n0 + bc;
    const h16* pu1 = Wu + (size_t)(br + 32) * ldw + n0 + bc;

    uint32_t smb = (uint32_t)__cvta_generic_to_shared(sm);
    uint32_t dA0 = smb + (ar * LA + ac) * 2;
    uint32_t dA1 = smb + ((ar + 64) * LA + ac) * 2;
    uint32_t dB0 = smb + SZA + (br * LB + bc) * 2;
    uint32_t dB1 = smb + SZA + ((br + 32) * LB + bc) * 2;

    #define SW_ISSUE(s, k0)  {                                               \
        uint32_t o = (s) * STG;                                              \
        CP16(dA0 + o, pA0 + (k0));                                           \
        CP16(dA1 + o, pA1 + (k0));                                           \
        size_t ko = (size_t)(k0) * ldw;                                      \
        CP16(dB0 + o,       pg0 + ko);                                       \
        CP16(dB1 + o,       pg1 + ko);                                       \
        CP16(dB0 + o + SZB, pu0 + ko);                                       \
        CP16(dB1 + o + SZB, pu1 + ko); }

    FragC accG[2][2], accU[2][2];
    #pragma unroll
    for (int i = 0; i < 2; i++)
        #pragma unroll
        for (int j = 0; j < 2; j++) {
            wmma::fill_fragment(accG[i][j], 0.f);
            wmma::fill_fragment(accU[i][j], 0.f);
        }

    int warp = tid >> 5;
    int rowOff = (warp >> 2) * 32, colOff = (warp & 3) * 32;

    SW_ISSUE(0, 0); CP_COMMIT();
    SW_ISSUE(1, BK); CP_COMMIT();

    for (int t = 0; t < NT; t++) {
        if (t + 2 < NT) {
            SW_ISSUE((t + 2) % 3, (t + 2) * BK); CP_COMMIT();
            asm volatile("cp.async.wait_group 2;");
        } else if (t + 1 < NT) {
            asm volatile("cp.async.wait_group 1;");
        } else {
            asm volatile("cp.async.wait_group 0;");
        }
        __syncthreads();

        int s = t % 3;
        h16* sA  = (h16*)(sm + s * STG);
        h16* sBg = (h16*)(sm + s * STG + SZA);
        h16* sBu = (h16*)(sm + s * STG + SZA + SZB);

        #pragma unroll
        for (int kk = 0; kk < BK; kk += 16) {
            FragA fa[2];
            FragB fg[2], fu[2];
            #pragma unroll
            for (int i = 0; i < 2; i++)
                wmma::load_matrix_sync(fa[i], sA + (rowOff + 16 * i) * LA + kk, LA);
            #pragma unroll
            for (int j = 0; j < 2; j++) {
                wmma::load_matrix_sync(fg[j], sBg + kk * LB + colOff + 16 * j, LB);
                wmma::load_matrix_sync(fu[j], sBu + kk * LB + colOff + 16 * j, LB);
            }
            #pragma unroll
            for (int i = 0; i < 2; i++)
                #pragma unroll
                for (int j = 0; j < 2; j++) {
                    wmma::mma_sync(accG[i][j], fa[i], fg[j], accG[i][j]);
                    wmma::mma_sync(accU[i][j], fa[i], fu[j], accU[i][j]);
                }
        }
        __syncthreads();
    }

    // Epilogue: silu(g)*u -> fp16 (padded layout, full-tile store safe)
    float (*Ep)[BN + 4] = (float(*)[BN + 4])sm;
    #pragma unroll
    for (int i = 0; i < 2; i++)
        #pragma unroll
        for (int j = 0; j < 2; j++) {
            #pragma unroll
            for (int s2 = 0; s2 < accG[i][j].num_elements; s2++) {
                float g = accG[i][j].x[s2];
                float u = accU[i][j].x[s2];
                accG[i][j].x[s2] = g * u / (1.f + __expf(-g));
            }
            wmma::store_matrix_sync(&Ep[rowOff + 16 * i][colOff + 16 * j],
                                    accG[i][j], BN + 4, wmma::mem_row_major);
        }
    __syncthreads();
    size_t orow0 = (size_t)(routed ? (base + row0) : row0);
    #pragma unroll
    for (int i = 0; i < 8; i++) {
        int lin = tid + i * 512;
        int r = lin >> 5, c4 = lin & 31;
        uint2 h = cvt4h(*(float4*)&Ep[r][c4 * 4]);
        *(uint2*)(Oh + (orow0 + r) * ldw + n0 + c4 * 4) = h;
    }
    #undef SW_ISSUE
}

// ---------------- fused down GEMM (routed z<16 scatter->g_ya, shared z==16 ->out) ----------------
__global__ __launch_bounds__(512) void k_down_f(
    const h16* __restrict__ Act, const h16* __restrict__ Sha,
    const h16* __restrict__ Edh, const h16* __restrict__ Sdh,
    float* __restrict__ OutP)
{
    constexpr int BM = 128, BN = 128, BK = 64;
    constexpr int LA = 72, LB = 136;
    constexpr int SZA = BM * LA * 2;
    constexpr int SZB = BK * LB * 2;
    constexpr int STG = SZA + SZB;                  // 35840

    extern __shared__ char sm[];

    int nb = blockIdx.x, rb = blockIdx.y, z = blockIdx.z;
    bool routed = (z < N_EXP);

    int base, cnt, lda, NT;
    const h16 *Ah, *Wh;
    if (routed) {
        base = g_offsets[z]; cnt = g_counts[z]; lda = I_DIM; NT = I_DIM / BK;  // 8
        Ah = Act; Wh = Edh + (size_t)z * I_DIM * H_DIM;
    } else {
        base = 0; cnt = T_TOK; lda = SI_DIM; NT = SI_DIM / BK;                 // 16
        Ah = Sha; Wh = Sdh;
    }
    int row0 = rb * BM;
    if (row0 >= cnt) return;
    int n0 = nb * BN;

    int tid = threadIdx.x;
    int warp = tid >> 5;
    int rowOff = (warp >> 2) * 32, colOff = (warp & 3) * 32;

    int ar = tid >> 3, ac = (tid & 7) * 8;
    int br = tid >> 4, bc = (tid & 15) * 8;
    const h16* pA0 = Ah + (size_t)(base + row0 + ar)      * lda + ac;
    const h16* pA1 = Ah + (size_t)(base + row0 + ar + 64) * lda + ac;
    const h16* pb0 = Wh + (size_t)br        * H_DIM + n0 + bc;
    const h16* pb1 = Wh + (size_t)(br + 32) * H_DIM + n0 + bc;

    uint32_t smb = (uint32_t)__cvta_generic_to_shared(sm);
    uint32_t dA0 = smb + (ar * LA + ac) * 2;
    uint32_t dA1 = smb + ((ar + 64) * LA + ac) * 2;
    uint32_t dB0 = smb + SZA + (br * LB + bc) * 2;
    uint32_t dB1 = smb + SZA + ((br + 32) * LB + bc) * 2;

    #define DN_ISSUE(s, k0)  {                                               \
        uint32_t o = (s) * STG;                                              \
        CP16(dA0 + o, pA0 + (k0));                                           \
        CP16(dA1 + o, pA1 + (k0));                                           \
        size_t ko = (size_t)(k0) * H_DIM;                                    \
        CP16(dB0 + o, pb0 + ko);                                             \
        CP16(dB1 + o, pb1 + ko); }

    FragC acc[2][2];
    #pragma unroll
    for (int i = 0; i < 2; i++)
        #pragma unroll
        for (int j = 0; j < 2; j++) wmma::fill_fragment(acc[i][j], 0.f);

    DN_ISSUE(0, 0); CP_COMMIT();
    DN_ISSUE(1, BK); CP_COMMIT();

    for (int t = 0; t < NT; t++) {
        if (t + 2 < NT) {
            DN_ISSUE((t + 2) % 3, (t + 2) * BK); CP_COMMIT();
            asm volatile("cp.async.wait_group 2;");
        } else if (t + 1 < NT) {
            asm volatile("cp.async.wait_group 1;");
        } else {
            asm volatile("cp.async.wait_group 0;");
        }
        __syncthreads();

        int s = t % 3;
        h16* sA = (h16*)(sm + s * STG);
        h16* sB = (h16*)(sm + s * STG + SZA);

        #pragma unroll
        for (int kk = 0; kk < BK; kk += 16) {
            FragA fa[2];
            FragB fb[2];
            #pragma unroll
            for (int i = 0; i < 2; i++)
                wmma::load_matrix_sync(fa[i], sA + (rowOff + 16 * i) * LA + kk, LA);
            #pragma unroll
            for (int j = 0; j < 2; j++)
                wmma::load_matrix_sync(fb[j], sB + kk * LB + colOff + 16 * j, LB);
            #pragma unroll
            for (int i = 0; i < 2; i++)
                #pragma unroll
                for (int j = 0; j < 2; j++)
                    wmma::mma_sync(acc[i][j], fa[i], fb[j], acc[i][j]);
        }
        __syncthreads();
    }

    // Epilogue
    float (*Ep)[BN + 4] = (float(*)[BN + 4])sm;
    #pragma unroll
    for (int i = 0; i < 2; i++)
        #pragma unroll
        for (int j = 0; j < 2; j++)
            wmma::store_matrix_sync(&Ep[rowOff + 16 * i][colOff + 16 * j],
                                    acc[i][j], BN + 4, wmma::mem_row_major);
    __syncthreads();
    #pragma unroll
    for (int i = 0; i < 8; i++) {
        int lin = tid + i * 512;
        int r = lin >> 5, c4 = lin & 31;
        int local = row0 + r;
        if (routed) {
            if (local < cnt) {
                int a = g_perm[base + local];
                *(float4*)(g_ya + (size_t)a * H_DIM + n0 + c4 * 4) = *(float4*)&Ep[r][c4 * 4];
            }
        } else {
            *(float4*)(OutP + (size_t)local * H_DIM + n0 + c4 * 4) = *(float4*)&Ep[r][c4 * 4];
        }
    }
    #undef DN_ISSUE
}

// out[t] = shared_out[t] + sum_k w[t,k] * ya[t*4+k]
__global__ void k_combine(float* __restrict__ Out) {
    int lin = blockIdx.x * 256 + threadIdx.x;
    int t  = lin >> 8;
    int c4 = lin & 255;
    float4 acc = ((float4*)Out)[lin];
    #pragma unroll
    for (int k = 0; k < TOPK; k++) {
        float wv = g_topk_w[t * TOPK + k];
        float4 v = *(const float4*)(g_ya + (size_t)(t * TOPK + k) * H_DIM + c4 * 4);
        acc.x += wv * v.x; acc.y += wv * v.y; acc.z += wv * v.z; acc.w += wv * v.w;
    }
    ((float4*)Out)[lin] = acc;
}

// ---------------- launch ----------------
static h16* symaddr(const void* sym) {
    void* p = nullptr;
    cudaGetSymbolAddress(&p, sym);
    return (h16*)p;
}

extern "C" void kernel_launch(void* const* d_in, const int* in_sizes, int n_in,
                              void* d_out, int out_size)
{
    const float* x  = (const float*)d_in[0];
    const float* gw = (const float*)d_in[1];
    const float* eg = (const float*)d_in[2];
    const float* eu = (const float*)d_in[3];
    const float* ed = (const float*)d_in[4];
    const float* sg = (const float*)d_in[5];
    const float* su = (const float*)d_in[6];
    const float* sd = (const float*)d_in[7];
    float* out = (float*)d_out;

    h16 *xh  = symaddr(g_xh);
    h16 *egh = symaddr(g_egh), *euh = symaddr(g_euh), *edh = symaddr(g_edh);
    h16 *sgh = symaddr(g_sgh), *suh = symaddr(g_suh), *sdh = symaddr(g_sdh);
    h16 *act = symaddr(g_act), *sha = symaddr(g_sha);

    constexpr int SMEM_SW = 3 * 53248;            // 159744
    constexpr int SMEM_DN = 3 * 35840;            // 107520
    cudaFuncSetAttribute(k_swiglu_f, cudaFuncAttributeMaxDynamicSharedMemorySize, SMEM_SW);
    cudaFuncSetAttribute(k_down_f,   cudaFuncAttributeMaxDynamicSharedMemorySize, SMEM_DN);

    // prep args (7 fp16 conversions)
    CvtArgs a;
    {
        const float* srcs[7] = {x, eg, eu, ed, sg, su, sd};
        h16*         dsts[7] = {xh, egh, euh, edh, sgh, suh, sdh};
        size_t       ns[7]   = {(size_t)T_TOK * H_DIM,
                                (size_t)N_EXP * H_DIM * I_DIM,
                                (size_t)N_EXP * H_DIM * I_DIM,
                                (size_t)N_EXP * I_DIM * H_DIM,
                                (size_t)H_DIM * SI_DIM,
                                (size_t)H_DIM * SI_DIM,
                                (size_t)SI_DIM * H_DIM};
        for (int i = 0; i < 7; i++) {
            a.s[i]  = (const float4*)srcs[i];
            a.d[i]  = (uint2*)dsts[i];
            a.n4[i] = (int)(ns[i] / 4);
        }
    }

    k_init<<<1, 32>>>();
    // fused gate + all conversions: y=0 gate (x<2048), y=1..7 convert tensor y-1
    k_prep<<<dim3(8192, 8), 256>>>(x, gw, a);
    k_offsets<<<1, 1>>>();
    k_scatter<<<T_TOK / 256, 256>>>();

    // fused SwiGLU: z<16 routed experts (nb<4), z=16 shared expert
    k_swiglu_f<<<dim3(8, 16, N_EXP + 1), 512, SMEM_SW>>>(xh, egh, euh, sgh, suh, act, sha);

    // fused down: z<16 routed (scatter to g_ya), z=16 shared (writes d_out fully)
    k_down_f<<<dim3(8, 16, N_EXP + 1), 512, SMEM_DN>>>(act, sha, edh, sdh, out);

    k_combine<<<(T_TOK * H_DIM / 4) / 256, 256>>>(out);
}